// round 5
// baseline (speedup 1.0000x reference)
#include <cuda_runtime.h>
#include <math.h>

// ===== problem constants =====
#define Bn    32
#define Sn    2048
#define Dn    512
#define NCLSn 2
#define Hn    16
#define HDn   32
#define Rn    (Bn*Sn)      // 65536 rows
#define KS    19

// ===== scratch (static device globals; no allocations) =====
__device__ float g_kT[KS*Dn];          // summed mexican-hat kernel, [j][d]
__device__ float g_Ag[Dn*32];          // g-folded score matrix, [d][c]
__device__ float g_GA[32];
__device__ float g_BA[32];
__device__ float g_Gv[Dn];
__device__ float g_Bv[Dn];
__device__ float g_pos[Rn*Dn];         // 128 MB
__device__ float g_xnew[Rn*Dn];        // 128 MB
__device__ float g_partS[4*Rn];        // per-colblock row partial sums
__device__ float g_partQ[4*Rn];        // per-colblock row partial sumsq
__device__ float g_mean[Rn];
__device__ float g_rstd[Rn];
__device__ float g_z[Bn*32*Dn];        // 2 MB   z[b][c][d]
__device__ float g_P[Bn*32];
__device__ float g_Q[Bn*32];
__device__ float g_o[Bn*NCLSn*Dn];

// ===== tf32 helpers =====
__device__ __forceinline__ unsigned f2tf(float x) {
    unsigned u;
    asm("cvt.rna.tf32.f32 %0, %1;" : "=r"(u) : "f"(x));
    return u;
}
__device__ __forceinline__ void mma_tf32(float* c, const unsigned* a, const unsigned* b) {
    asm volatile(
        "mma.sync.aligned.m16n8k8.row.col.f32.tf32.tf32.f32 "
        "{%0,%1,%2,%3},{%4,%5,%6,%7},{%8,%9},{%0,%1,%2,%3};"
        : "+f"(c[0]), "+f"(c[1]), "+f"(c[2]), "+f"(c[3])
        : "r"(a[0]), "r"(a[1]), "r"(a[2]), "r"(a[3]), "r"(b[0]), "r"(b[1]));
}

// ===== prep: summed mexican-hat kernel =====
__global__ void k_prep_ksum(const float* __restrict__ w1,
                            const float* __restrict__ w2,
                            const float* __restrict__ w3) {
    int d = threadIdx.x;
    const float C = 0.8673250705840776f;  // 2/(sqrt(3)*pi^0.25)
    float out[KS];
    #pragma unroll
    for (int j = 0; j < KS; j++) out[j] = 0.f;
    const float* ws[3] = {w1, w2, w3};
    for (int w = 0; w < 3; w++) {
        float scale = ws[w][d];
        float shift = ws[w][Dn + d];
        float inv   = 1.f / scale;
        float amp   = C * rsqrtf(fabsf(scale));
        #pragma unroll
        for (int j = 0; j < KS; j++) {
            float xg = (float)(j - 9) - shift;
            float u  = xg * inv;
            out[j] += amp * (1.f - u * u) * expf(-0.5f * u * u);
        }
    }
    #pragma unroll
    for (int j = 0; j < KS; j++) g_kT[j * Dn + d] = out[j];
}

// ===== merged prep: q = cls@Wq; Ag; GA; BA. One block, 1024 threads =====
__global__ void __launch_bounds__(1024)
k_prep_qA(const float* __restrict__ cls, const float* __restrict__ Wq,
          const float* __restrict__ Wkv, const float* __restrict__ g1,
          const float* __restrict__ b1) {
    __shared__ float sq[NCLSn * Dn];
    __shared__ float ra[32][33];
    __shared__ float rb[32][33];
    int t = threadIdx.x;

    // phase 1: q
    {
        int n = t >> 9, dp = t & 511;
        float acc = 0.f;
        #pragma unroll 4
        for (int d = 0; d < Dn; d++)
            acc += cls[n * Dn + d] * Wq[d * Dn + dp];
        sq[n * Dn + dp] = acc;
    }
    __syncthreads();

    // phase 2: Ag rows + GA/BA partials
    int c = t & 31;
    int h = c >> 1, n = c & 1;
    int dg = t >> 5;                  // 0..31
    float ga = 0.f, ba = 0.f;
    #pragma unroll
    for (int p = 0; p < 16; p++) {
        int d = dg + p * 32;
        float acc = 0.f;
        #pragma unroll
        for (int hd = 0; hd < HDn; hd++)
            acc += Wkv[(size_t)d * (2 * Dn) + h * HDn + hd] * sq[n * Dn + h * HDn + hd];
        acc *= 0.17677669529663687f;  // HD^-0.5
        float ag = g1[d] * acc;
        g_Ag[d * 32 + c] = ag;
        ga += ag;
        ba += b1[d] * acc;
    }
    ra[dg][c] = ga;
    rb[dg][c] = ba;
    __syncthreads();
    if (t < 32) {
        float sga = 0.f, sba = 0.f;
        #pragma unroll
        for (int k = 0; k < 32; k++) { sga += ra[k][t]; sba += rb[k][t]; }
        g_GA[t] = sga;
        g_BA[t] = sba;
    }
}

// ===== Gv/Bv directly from Wkv =====
__global__ void k_prep_vvec(const float* __restrict__ Wkv,
                            const float* __restrict__ g1,
                            const float* __restrict__ b1) {
    int j = blockIdx.x * 128 + threadIdx.x;
    float gv = 0.f, bv = 0.f;
    #pragma unroll 4
    for (int d = 0; d < Dn; d++) {
        float w = Wkv[(size_t)d * (2 * Dn) + Dn + j];
        gv += g1[d] * w;
        bv += b1[d] * w;
    }
    g_Gv[j] = gv;
    g_Bv[j] = bv;
}

// ===== depthwise conv: 16 outputs/thread (halo overlap 2.1x) =====
__global__ void __launch_bounds__(512)
k_conv(const float* __restrict__ x) {
    int chunk = blockIdx.x;            // 0..4095
    int b  = chunk >> 7;               // 128 chunks per batch
    int s0 = (chunk & 127) * 16;
    int d  = threadIdx.x;
    const float* xb = x + (size_t)b * Sn * Dn;

    float w[KS];
    #pragma unroll
    for (int j = 0; j < KS; j++) w[j] = g_kT[j * Dn + d];

    float xv[34];
    #pragma unroll
    for (int l = 0; l < 34; l++) {
        int ss = s0 - 9 + l;
        xv[l] = ((unsigned)ss < (unsigned)Sn) ? xb[(size_t)ss * Dn + d] : 0.f;
    }
    float* pb = g_pos + ((size_t)(b * Sn + s0)) * Dn + d;
    #pragma unroll
    for (int o = 0; o < 16; o++) {
        float acc = 0.f;
        #pragma unroll
        for (int j = 0; j < KS; j++) acc += xv[o + j] * w[j];
        pb[(size_t)o * Dn] = acc;
    }
}

// ===== GEMM0 (tf32 TC): xnew = pos @ Wp1 + x + bp1; emits LN partials =====
// 128x128 block tile, K-tile 16, 8 warps (64x32 warp tile), mma.m16n8k8
// As: [m][k] pad-20 (STS.128 stores, conflict-free a-frag LDS)
// Bs: [k][n] pad-136 (STS.128 stores, conflict-free b-frag LDS)
#define APAD 20
#define BPAD 136
__global__ void __launch_bounds__(256)
k_gemm0(const float* __restrict__ Wp1, const float* __restrict__ X,
        const float* __restrict__ bias) {
    __shared__ unsigned As[2][128][APAD];
    __shared__ unsigned Bs[2][16][BPAD];
    int t    = threadIdx.x;
    int brow = blockIdx.y * 128;
    int bcol = blockIdx.x * 128;
    int lane = t & 31, warp = t >> 5;
    int g    = lane >> 2, tig = lane & 3;
    int m0w  = (warp >> 2) * 64;
    int n0w  = (warp & 3) * 32;

    int arow = t >> 1, akh = (t & 1) * 8;
    int bkr  = t >> 4, bn8 = (t & 15) * 8;

    const float* pA = g_pos + (size_t)(brow + arow) * Dn + akh;
    const float* pB = Wp1 + (size_t)bkr * Dn + bcol + bn8;

    float acc[4][4][4];
    #pragma unroll
    for (int i = 0; i < 4; i++)
        #pragma unroll
        for (int j = 0; j < 4; j++)
            #pragma unroll
            for (int k = 0; k < 4; k++) acc[i][j][k] = 0.f;

    {
        float4 A0 = *(const float4*)(pA);
        float4 A1 = *(const float4*)(pA + 4);
        float4 B0 = *(const float4*)(pB);
        float4 B1 = *(const float4*)(pB + 4);
        uint4 u;
        u.x = f2tf(A0.x); u.y = f2tf(A0.y); u.z = f2tf(A0.z); u.w = f2tf(A0.w);
        *(uint4*)&As[0][arow][akh] = u;
        u.x = f2tf(A1.x); u.y = f2tf(A1.y); u.z = f2tf(A1.z); u.w = f2tf(A1.w);
        *(uint4*)&As[0][arow][akh + 4] = u;
        u.x = f2tf(B0.x); u.y = f2tf(B0.y); u.z = f2tf(B0.z); u.w = f2tf(B0.w);
        *(uint4*)&Bs[0][bkr][bn8] = u;
        u.x = f2tf(B1.x); u.y = f2tf(B1.y); u.z = f2tf(B1.z); u.w = f2tf(B1.w);
        *(uint4*)&Bs[0][bkr][bn8 + 4] = u;
    }
    __syncthreads();

    int buf = 0;
    for (int kt = 1; kt <= 32; kt++) {
        bool more = (kt < 32);
        float4 A0, A1, B0, B1;
        if (more) {
            int k0 = kt * 16;
            A0 = *(const float4*)(pA + k0);
            A1 = *(const float4*)(pA + k0 + 4);
            B0 = *(const float4*)(pB + (size_t)k0 * Dn);
            B1 = *(const float4*)(pB + (size_t)k0 * Dn + 4);
        }
        #pragma unroll
        for (int ks = 0; ks < 16; ks += 8) {
            unsigned a[4][4], b[4][2];
            #pragma unroll
            for (int i = 0; i < 4; i++) {
                int m = m0w + 16 * i + g;
                a[i][0] = As[buf][m][ks + tig];
                a[i][1] = As[buf][m + 8][ks + tig];
                a[i][2] = As[buf][m][ks + tig + 4];
                a[i][3] = As[buf][m + 8][ks + tig + 4];
            }
            #pragma unroll
            for (int j = 0; j < 4; j++) {
                int n = n0w + 8 * j + g;
                b[j][0] = Bs[buf][ks + tig][n];
                b[j][1] = Bs[buf][ks + tig + 4][n];
            }
            #pragma unroll
            for (int i = 0; i < 4; i++)
                #pragma unroll
                for (int j = 0; j < 4; j++)
                    mma_tf32(acc[i][j], a[i], b[j]);
        }
        if (more) {
            int nb = buf ^ 1;
            uint4 u;
            u.x = f2tf(A0.x); u.y = f2tf(A0.y); u.z = f2tf(A0.z); u.w = f2tf(A0.w);
            *(uint4*)&As[nb][arow][akh] = u;
            u.x = f2tf(A1.x); u.y = f2tf(A1.y); u.z = f2tf(A1.z); u.w = f2tf(A1.w);
            *(uint4*)&As[nb][arow][akh + 4] = u;
            u.x = f2tf(B0.x); u.y = f2tf(B0.y); u.z = f2tf(B0.z); u.w = f2tf(B0.w);
            *(uint4*)&Bs[nb][bkr][bn8] = u;
            u.x = f2tf(B1.x); u.y = f2tf(B1.y); u.z = f2tf(B1.z); u.w = f2tf(B1.w);
            *(uint4*)&Bs[nb][bkr][bn8 + 4] = u;
        }
        __syncthreads();
        buf ^= 1;
    }

    // epilogue: out = acc + X + bias; accumulate per-row partial sum/sumsq
    float rs1[4], rq1[4], rs2[4], rq2[4];
    #pragma unroll
    for (int i = 0; i < 4; i++) { rs1[i] = rq1[i] = rs2[i] = rq2[i] = 0.f; }

    #pragma unroll
    for (int i = 0; i < 4; i++) {
        #pragma unroll
        for (int j = 0; j < 4; j++) {
            int r1 = brow + m0w + 16 * i + g;
            int r2 = r1 + 8;
            int cc = bcol + n0w + 8 * j + 2 * tig;
            float2 bb = *(const float2*)(bias + cc);
            float2 x1 = *(const float2*)(X + (size_t)r1 * Dn + cc);
            float2 o1 = make_float2(acc[i][j][0] + x1.x + bb.x,
                                    acc[i][j][1] + x1.y + bb.y);
            *(float2*)(g_xnew + (size_t)r1 * Dn + cc) = o1;
            rs1[i] += o1.x + o1.y;
            rq1[i] += o1.x * o1.x + o1.y * o1.y;
            float2 x2 = *(const float2*)(X + (size_t)r2 * Dn + cc);
            float2 o2 = make_float2(acc[i][j][2] + x2.x + bb.x,
                                    acc[i][j][3] + x2.y + bb.y);
            *(float2*)(g_xnew + (size_t)r2 * Dn + cc) = o2;
            rs2[i] += o2.x + o2.y;
            rq2[i] += o2.x * o2.x + o2.y * o2.y;
        }
    }
    #pragma unroll
    for (int i = 0; i < 4; i++) {
        rs1[i] += __shfl_down_sync(0xffffffffu, rs1[i], 2);
        rs1[i] += __shfl_down_sync(0xffffffffu, rs1[i], 1);
        rq1[i] += __shfl_down_sync(0xffffffffu, rq1[i], 2);
        rq1[i] += __shfl_down_sync(0xffffffffu, rq1[i], 1);
        rs2[i] += __shfl_down_sync(0xffffffffu, rs2[i], 2);
        rs2[i] += __shfl_down_sync(0xffffffffu, rs2[i], 1);
        rq2[i] += __shfl_down_sync(0xffffffffu, rq2[i], 2);
        rq2[i] += __shfl_down_sync(0xffffffffu, rq2[i], 1);
    }
    float* sp  = (float*)&As[0][0][0];
    float* sqm = sp + 512;
    int nj = warp & 3;
    if (tig == 0) {
        #pragma unroll
        for (int i = 0; i < 4; i++) {
            int rl1 = m0w + 16 * i + g;
            sp[nj * 128 + rl1]       = rs1[i];
            sqm[nj * 128 + rl1]      = rq1[i];
            sp[nj * 128 + rl1 + 8]   = rs2[i];
            sqm[nj * 128 + rl1 + 8]  = rq2[i];
        }
    }
    __syncthreads();
    if (t < 128) {
        float s  = sp[t] + sp[128 + t] + sp[256 + t] + sp[384 + t];
        float ss = sqm[t] + sqm[128 + t] + sqm[256 + t] + sqm[384 + t];
        g_partS[(size_t)blockIdx.x * Rn + brow + t] = s;
        g_partQ[(size_t)blockIdx.x * Rn + brow + t] = ss;
    }
}

// ===== scores (+ folded LN stats): 256 rows x 32 cols per block =====
__global__ void __launch_bounds__(256)
k_scores(float* __restrict__ attn_out) {
    __shared__ float Xs[32][260];
    __shared__ float As2[32][32];
    __shared__ float sm_mean[256];
    __shared__ float sm_rstd[256];
    int t  = threadIdx.x;
    int R0 = blockIdx.x * 256;
    int rgrp = t & 31, cgrp = t >> 5;
    int r0 = rgrp * 8, c0 = cgrp * 4;

    // fold rowstats: each block finalizes LN stats for its 256 rows
    {
        int r = R0 + t;
        float s  = g_partS[r] + g_partS[Rn + r] + g_partS[2 * Rn + r] + g_partS[3 * Rn + r];
        float ss = g_partQ[r] + g_partQ[Rn + r] + g_partQ[2 * Rn + r] + g_partQ[3 * Rn + r];
        float m   = s * (1.f / Dn);
        float var = ss * (1.f / Dn) - m * m;
        float rs  = rsqrtf(var + 1e-5f);
        g_mean[r] = m;
        g_rstd[r] = rs;
        sm_mean[t] = m;
        sm_rstd[t] = rs;
    }

    float acc[8][4];
    #pragma unroll
    for (int i = 0; i < 8; i++)
        #pragma unroll
        for (int j = 0; j < 4; j++) acc[i][j] = 0.f;

    for (int dt = 0; dt < 16; dt++) {
        #pragma unroll
        for (int i = 0; i < 8; i++) {
            int rr  = (t >> 3) + i * 32;
            int dd0 = (t & 7) * 4;
            float4 a4 = *(const float4*)(g_xnew + (size_t)(R0 + rr) * Dn + dt * 32 + dd0);
            Xs[dd0 + 0][rr] = a4.x;
            Xs[dd0 + 1][rr] = a4.y;
            Xs[dd0 + 2][rr] = a4.z;
            Xs[dd0 + 3][rr] = a4.w;
        }
        {
            int dp = t >> 3, c4 = (t & 7) * 4;
            *(float4*)&As2[dp][c4] = *(const float4*)(g_Ag + (dt * 32 + dp) * 32 + c4);
        }
        __syncthreads();
        #pragma unroll
        for (int dd = 0; dd < 32; dd++) {
            float xa[8], ab[4];
            *(float4*)&xa[0] = *(const float4*)&Xs[dd][r0];
            *(float4*)&xa[4] = *(const float4*)&Xs[dd][r0 + 4];
            *(float4*)&ab[0] = *(const float4*)&As2[dd][c0];
            #pragma unroll
            for (int i = 0; i < 8; i++)
                #pragma unroll
                for (int j = 0; j < 4; j++) acc[i][j] += xa[i] * ab[j];
        }
        __syncthreads();
    }

    #pragma unroll
    for (int i = 0; i < 8; i++) {
        int rl = r0 + i;
        int gr = R0 + rl;
        float rs = sm_rstd[rl], mn = sm_mean[rl];
        int b = gr >> 11, s = gr & 2047;
        #pragma unroll
        for (int j = 0; j < 4; j++) {
            int c = c0 + j;
            float sc = rs * (acc[i][j] - mn * g_GA[c]) + g_BA[c]
                       - 7.6246189861593985f;
            float a = 1.f / (1.f + expf(-sc));
            attn_out[((size_t)(b * 32 + c)) * Sn + s] = a;
        }
    }
}

// ===== P,Q per (b,c) =====
__global__ void k_pq(const float* __restrict__ attn) {
    int b = blockIdx.x;
    int t = threadIdx.x;
    int c = t >> 3, sg = t & 7;
    const float* ar = attn + ((size_t)(b * 32 + c)) * Sn;
    const float* rsd = g_rstd + b * Sn;
    const float* mnp = g_mean + b * Sn;
    float P = 0.f, Q = 0.f;
    for (int s = sg; s < Sn; s += 8) {
        float a = ar[s];
        P += a;
        Q += a * rsd[s] * mnp[s];
    }
    __shared__ float redP[256], redQ[256];
    redP[t] = P; redQ[t] = Q;
    __syncthreads();
    if (t < 32) {
        float p = 0.f, q = 0.f;
        #pragma unroll
        for (int k = 0; k < 8; k++) { p += redP[t * 8 + k]; q += redQ[t * 8 + k]; }
        g_P[b * 32 + t] = p;
        g_Q[b * 32 + t] = q;
    }
}

// ===== z[b,c,d] = sum_s attn[b,c,s]*rstd[b,s]*xnew[b,s,d] =====
__global__ void __launch_bounds__(256)
k_z(const float* __restrict__ attn) {
    __shared__ float a_sm[32][36];
    int t  = threadIdx.x;
    int d0 = blockIdx.x * 128;
    int b  = blockIdx.y;
    int cq = t >> 5;
    int dq = t & 31;
    int c0 = cq * 4;
    int d  = d0 + dq * 4;

    float acc[4][4];
    #pragma unroll
    for (int j = 0; j < 4; j++)
        #pragma unroll
        for (int k = 0; k < 4; k++) acc[j][k] = 0.f;

    for (int s0 = 0; s0 < Sn; s0 += 32) {
        {
            int c  = t >> 3;
            int s4 = (t & 7) * 4;
            float4 a4 = *(const float4*)(attn + ((size_t)(b * 32 + c)) * Sn + s0 + s4);
            const float* rsd = g_rstd + b * Sn + s0 + s4;
            a4.x *= rsd[0]; a4.y *= rsd[1]; a4.z *= rsd[2]; a4.w *= rsd[3];
            *(float4*)&a_sm[c][s4] = a4;
        }
        __syncthreads();
        #pragma unroll 8
        for (int si = 0; si < 32; si++) {
            float4 xv = *(const float4*)(g_xnew + (size_t)(b * Sn + s0 + si) * Dn + d);
            #pragma unroll
            for (int j = 0; j < 4; j++) {
                float av = a_sm[c0 + j][si];
                acc[j][0] += av * xv.x;
                acc[j][1] += av * xv.y;
                acc[j][2] += av * xv.z;
                acc[j][3] += av * xv.w;
            }
        }
        __syncthreads();
    }
    #pragma unroll
    for (int j = 0; j < 4; j++) {
        float4 o4 = make_float4(acc[j][0], acc[j][1], acc[j][2], acc[j][3]);
        *(float4*)(g_z + (size_t)(b * 32 + c0 + j) * Dn + d) = o4;
    }
}

// ===== o[b,n,j] = (z*g1)·Wkv[:,Dn+j] - Q*Gv[j] + P*Bv[j] =====
__global__ void __launch_bounds__(256)
k_o(const float* __restrict__ Wkv, const float* __restrict__ g1) {
    __shared__ float zs[16][512];
    __shared__ float sg1[512];
    int b = blockIdx.x, n = blockIdx.y;
    int t = threadIdx.x;
    int hh = t >> 5;
    int hd = t & 31;

    sg1[t] = g1[t];
    sg1[t + 256] = g1[t + 256];
    __syncthreads();
    for (int idx = t; idx < 16 * 512; idx += 256) {
        int h = idx >> 9, d = idx & 511;
        zs[h][d] = g_z[(size_t)(b * 32 + h * 2 + n) * Dn + d] * sg1[d];
    }
    __syncthreads();

    #pragma unroll
    for (int hi = 0; hi < 2; hi++) {
        int h = hh + hi * 8;
        int j = h * HDn + hd;
        float acc = 0.f;
        for (int d = 0; d < Dn; d++)
            acc += zs[h][d] * Wkv[(size_t)d * (2 * Dn) + Dn + j];
        int c = h * 2 + n;
        float o = acc - g_Q[b * 32 + c] * g_Gv[j] + g_P[b * 32 + c] * g_Bv[j];
        g_o[(b * NCLSn + n) * Dn + j] = o;
    }
}

// ===== head: proj + LN + MLP -> logits, one block per (b,n) =====
__global__ void __launch_bounds__(256)
k_head(const float* __restrict__ Wproj, const float* __restrict__ bproj,
       const float* __restrict__ g2, const float* __restrict__ b2,
       const float* __restrict__ Wc1, const float* __restrict__ bc1,
       const float* __restrict__ Wc2, const float* __restrict__ bc2,
       float* __restrict__ out) {
    int bn = blockIdx.x;
    int t  = threadIdx.x;
    __shared__ float row[Dn];
    __shared__ float tmp[Dn];
    __shared__ float red[256];

    row[t]       = g_o[bn * Dn + t];
    row[t + 256] = g_o[bn * Dn + t + 256];
    __syncthreads();

    float a0 = 0.f, a1 = 0.f;
    for (int d = 0; d < Dn; d++) {
        float rv = row[d];
        a0 += rv * Wproj[d * Dn + t];
        a1 += rv * Wproj[d * Dn + t + 256];
    }
    tmp[t]       = a0 + bproj[t];
    tmp[t + 256] = a1 + bproj[t + 256];
    __syncthreads();

    float ps  = tmp[t] + tmp[t + 256];
    float pss = tmp[t] * tmp[t] + tmp[t + 256] * tmp[t + 256];
    red[t] = ps; __syncthreads();
    for (int o = 128; o > 0; o >>= 1) { if (t < o) red[t] += red[t + o]; __syncthreads(); }
    float mean = red[0] * (1.f / Dn);
    __syncthreads();
    red[t] = pss; __syncthreads();
    for (int o = 128; o > 0; o >>= 1) { if (t < o) red[t] += red[t + o]; __syncthreads(); }
    float var  = red[0] * (1.f / Dn) - mean * mean;
    float rstd = rsqrtf(var + 1e-5f);
    __syncthreads();

    row[t]       = (tmp[t] - mean) * rstd * g2[t] + b2[t];
    row[t + 256] = (tmp[t + 256] - mean) * rstd * g2[t + 256] + b2[t + 256];
    __syncthreads();

    float c0 = 0.f, c1 = 0.f;
    for (int d = 0; d < Dn; d++) {
        float rv = row[d];
        c0 += rv * Wc1[d * Dn + t];
        c1 += rv * Wc1[d * Dn + t + 256];
    }
    c0 = fmaxf(c0 + bc1[t], 0.f);
    c1 = fmaxf(c1 + bc1[t + 256], 0.f);
    float part = c0 * Wc2[t] + c1 * Wc2[t + 256];
    red[t] = part; __syncthreads();
    for (int o = 128; o > 0; o >>= 1) { if (t < o) red[t] += red[t + o]; __syncthreads(); }
    if (t == 0) out[bn] = red[0] + bc2[0];
}

// ===== launch =====
extern "C" void kernel_launch(void* const* d_in, const int* in_sizes, int n_in,
                              void* d_out, int out_size) {
    const float* x     = (const float*)d_in[0];
    const float* wave1 = (const float*)d_in[1];
    const float* wave2 = (const float*)d_in[2];
    const float* wave3 = (const float*)d_in[3];
    const float* Wp1   = (const float*)d_in[4];
    const float* bp1   = (const float*)d_in[5];
    const float* cls   = (const float*)d_in[6];
    const float* ln1g  = (const float*)d_in[7];
    const float* ln1b  = (const float*)d_in[8];
    const float* Wq    = (const float*)d_in[9];
    const float* Wkv   = (const float*)d_in[10];
    const float* Wproj = (const float*)d_in[11];
    const float* bproj = (const float*)d_in[12];
    const float* ln2g  = (const float*)d_in[13];
    const float* ln2b  = (const float*)d_in[14];
    const float* Wc1   = (const float*)d_in[15];
    const float* bc1   = (const float*)d_in[16];
    const float* Wc2   = (const float*)d_in[17];
    const float* bc2   = (const float*)d_in[18];
    float* out = (float*)d_out;
    float* attn = out + Bn * NCLSn;   // logits first, then attn [B,H,NCLS,S]

    k_prep_ksum<<<1, 512>>>(wave1, wave2, wave3);                 // 1
    k_conv<<<Rn / 16, 512>>>(x);                                  // 2
    k_prep_qA<<<1, 1024>>>(cls, Wq, Wkv, ln1g, ln1b);             // 3
    k_gemm0<<<dim3(4, 512), 256>>>(Wp1, x, bp1);                  // 4  <- profiled
    k_prep_vvec<<<4, 128>>>(Wkv, ln1g, ln1b);                     // 5
    k_scores<<<256, 256>>>(attn);                                 // 6 (stats folded in)
    k_pq<<<Bn, 256>>>(attn);                                      // 7
    k_z<<<dim3(4, Bn), 256>>>(attn);                              // 8
    k_o<<<dim3(Bn, NCLSn), 256>>>(Wkv, ln1g);                     // 9
    k_head<<<64, 256>>>(Wproj, bproj, ln2g, ln2b, Wc1, bc1, Wc2, bc2, out); // 10
}

// round 7
// speedup vs baseline: 1.0658x; 1.0658x over previous
#include <cuda_runtime.h>
#include <math.h>

// ===== problem constants =====
#define Bn    32
#define Sn    2048
#define Dn    512
#define NCLSn 2
#define Hn    16
#define HDn   32
#define Rn    (Bn*Sn)      // 65536 rows
#define KS    19

// ===== scratch =====
__device__ float g_kT[KS*Dn];
__device__ float g_Ag[Dn*32];
__device__ float g_GA[32];
__device__ float g_BA[32];
__device__ float g_Gv[Dn];
__device__ float g_Bv[Dn];
__device__ float g_pos[Rn*Dn];         // 128 MB
__device__ float g_xnew[Rn*Dn];        // 128 MB
__device__ float g_mean[Rn];
__device__ float g_rstd[Rn];
__device__ float g_z[Bn*32*Dn];        // 2 MB
__device__ float g_P[Bn*32];
__device__ float g_Q[Bn*32];

// ===== tf32 helpers =====
__device__ __forceinline__ unsigned f2tf(float x) {
    unsigned u;
    asm("cvt.rna.tf32.f32 %0, %1;" : "=r"(u) : "f"(x));
    return u;
}
__device__ __forceinline__ void mma_tf32(float* c, const unsigned* a, const unsigned* b) {
    asm volatile(
        "mma.sync.aligned.m16n8k8.row.col.f32.tf32.tf32.f32 "
        "{%0,%1,%2,%3},{%4,%5,%6,%7},{%8,%9},{%0,%1,%2,%3};"
        : "+f"(c[0]), "+f"(c[1]), "+f"(c[2]), "+f"(c[3])
        : "r"(a[0]), "r"(a[1]), "r"(a[2]), "r"(a[3]), "r"(b[0]), "r"(b[1]));
}

// ===== prep: summed mexican-hat kernel =====
__global__ void k_prep_ksum(const float* __restrict__ w1,
                            const float* __restrict__ w2,
                            const float* __restrict__ w3) {
    int d = threadIdx.x;
    const float C = 0.8673250705840776f;
    float out[KS];
    #pragma unroll
    for (int j = 0; j < KS; j++) out[j] = 0.f;
    const float* ws[3] = {w1, w2, w3};
    for (int w = 0; w < 3; w++) {
        float scale = ws[w][d];
        float shift = ws[w][Dn + d];
        float inv   = 1.f / scale;
        float amp   = C * rsqrtf(fabsf(scale));
        #pragma unroll
        for (int j = 0; j < KS; j++) {
            float xg = (float)(j - 9) - shift;
            float u  = xg * inv;
            out[j] += amp * (1.f - u * u) * expf(-0.5f * u * u);
        }
    }
    #pragma unroll
    for (int j = 0; j < KS; j++) g_kT[j * Dn + d] = out[j];
}

// ===== merged prep: q = cls@Wq; Ag; GA; BA =====
__global__ void __launch_bounds__(1024)
k_prep_qA(const float* __restrict__ cls, const float* __restrict__ Wq,
          const float* __restrict__ Wkv, const float* __restrict__ g1,
          const float* __restrict__ b1) {
    __shared__ float sq[NCLSn * Dn];
    __shared__ float ra[32][33];
    __shared__ float rb[32][33];
    int t = threadIdx.x;
    {
        int n = t >> 9, dp = t & 511;
        float acc = 0.f;
        #pragma unroll 4
        for (int d = 0; d < Dn; d++)
            acc += cls[n * Dn + d] * Wq[d * Dn + dp];
        sq[n * Dn + dp] = acc;
    }
    __syncthreads();
    int c = t & 31;
    int h = c >> 1, n = c & 1;
    int dg = t >> 5;
    float ga = 0.f, ba = 0.f;
    #pragma unroll
    for (int p = 0; p < 16; p++) {
        int d = dg + p * 32;
        float acc = 0.f;
        #pragma unroll
        for (int hd = 0; hd < HDn; hd++)
            acc += Wkv[(size_t)d * (2 * Dn) + h * HDn + hd] * sq[n * Dn + h * HDn + hd];
        acc *= 0.17677669529663687f;
        float ag = g1[d] * acc;
        g_Ag[d * 32 + c] = ag;
        ga += ag;
        ba += b1[d] * acc;
    }
    ra[dg][c] = ga;
    rb[dg][c] = ba;
    __syncthreads();
    if (t < 32) {
        float sga = 0.f, sba = 0.f;
        #pragma unroll
        for (int k = 0; k < 32; k++) { sga += ra[k][t]; sba += rb[k][t]; }
        g_GA[t] = sga;
        g_BA[t] = sba;
    }
}

// ===== Gv/Bv from Wkv =====
__global__ void k_prep_vvec(const float* __restrict__ Wkv,
                            const float* __restrict__ g1,
                            const float* __restrict__ b1) {
    int j = blockIdx.x * 128 + threadIdx.x;
    float gv = 0.f, bv = 0.f;
    #pragma unroll 4
    for (int d = 0; d < Dn; d++) {
        float w = Wkv[(size_t)d * (2 * Dn) + Dn + j];
        gv += g1[d] * w;
        bv += b1[d] * w;
    }
    g_Gv[j] = gv;
    g_Bv[j] = bv;
}

// ===== depthwise conv: 16 outputs/thread =====  (PROFILED SLOT)
__global__ void __launch_bounds__(512)
k_conv(const float* __restrict__ x) {
    int chunk = blockIdx.x;
    int b  = chunk >> 7;
    int s0 = (chunk & 127) * 16;
    int d  = threadIdx.x;
    const float* xb = x + (size_t)b * Sn * Dn;

    float w[KS];
    #pragma unroll
    for (int j = 0; j < KS; j++) w[j] = g_kT[j * Dn + d];

    float xv[34];
    #pragma unroll
    for (int l = 0; l < 34; l++) {
        int ss = s0 - 9 + l;
        xv[l] = ((unsigned)ss < (unsigned)Sn) ? xb[(size_t)ss * Dn + d] : 0.f;
    }
    float* pb = g_pos + ((size_t)(b * Sn + s0)) * Dn + d;
    #pragma unroll
    for (int o = 0; o < 16; o++) {
        float acc = 0.f;
        #pragma unroll
        for (int j = 0; j < KS; j++) acc += xv[o + j] * w[j];
        pb[(size_t)o * Dn] = acc;
    }
}

// ===== GEMM0 (tf32 TC): xnew = pos @ Wp1 + x + bp1 =====
// 128x128 block tile, 4 warps of 64x64 warp tiles, K-tile 16, mma.m16n8k8
#define APAD 20
#define BPAD 136
__global__ void __launch_bounds__(128)
k_gemm0(const float* __restrict__ Wp1, const float* __restrict__ X,
        const float* __restrict__ bias) {
    __shared__ unsigned As[2][128][APAD];   // [m][k]
    __shared__ unsigned Bs[2][16][BPAD];    // [k][n]
    int t    = threadIdx.x;
    int brow = blockIdx.y * 128;
    int bcol = blockIdx.x * 128;
    int lane = t & 31, warp = t >> 5;
    int g    = lane >> 2, tig = lane & 3;
    int m0w  = (warp >> 1) * 64;
    int n0w  = (warp & 1) * 64;

    int arow = t;                     // A fill: row per thread, 16 k
    int bkr  = t & 15;                // B fill: k-row
    int bn16 = (t >> 4) * 16;         // B fill: n-offset (16 per thread)

    const float* pA = g_pos + (size_t)(brow + arow) * Dn;
    const float* pB = Wp1 + (size_t)bkr * Dn + bcol + bn16;

    float acc[4][8][4];
    #pragma unroll
    for (int i = 0; i < 4; i++)
        #pragma unroll
        for (int j = 0; j < 8; j++)
            #pragma unroll
            for (int k = 0; k < 4; k++) acc[i][j][k] = 0.f;

    // prologue tile 0
    {
        #pragma unroll
        for (int q = 0; q < 4; q++) {
            float4 a4 = *(const float4*)(pA + q * 4);
            uint4 u;
            u.x = f2tf(a4.x); u.y = f2tf(a4.y); u.z = f2tf(a4.z); u.w = f2tf(a4.w);
            *(uint4*)&As[0][arow][q * 4] = u;
        }
        #pragma unroll
        for (int q = 0; q < 4; q++) {
            float4 b4 = *(const float4*)(pB + q * 4);
            uint4 u;
            u.x = f2tf(b4.x); u.y = f2tf(b4.y); u.z = f2tf(b4.z); u.w = f2tf(b4.w);
            *(uint4*)&Bs[0][bkr][bn16 + q * 4] = u;
        }
    }
    __syncthreads();

    int buf = 0;
    for (int kt = 1; kt <= 32; kt++) {
        bool more = (kt < 32);
        float4 Apre[4], Bpre[4];
        if (more) {
            int k0 = kt * 16;
            #pragma unroll
            for (int q = 0; q < 4; q++) {
                Apre[q] = *(const float4*)(pA + k0 + q * 4);
                Bpre[q] = *(const float4*)(pB + (size_t)k0 * Dn + q * 4);
            }
        }
        #pragma unroll
        for (int ks = 0; ks < 16; ks += 8) {
            unsigned a[4][4], b[8][2];
            #pragma unroll
            for (int i = 0; i < 4; i++) {
                int m = m0w + 16 * i + g;
                a[i][0] = As[buf][m][ks + tig];
                a[i][1] = As[buf][m + 8][ks + tig];
                a[i][2] = As[buf][m][ks + tig + 4];
                a[i][3] = As[buf][m + 8][ks + tig + 4];
            }
            #pragma unroll
            for (int j = 0; j < 8; j++) {
                int n = n0w + 8 * j + g;
                b[j][0] = Bs[buf][ks + tig][n];
                b[j][1] = Bs[buf][ks + tig + 4][n];
            }
            #pragma unroll
            for (int i = 0; i < 4; i++)
                #pragma unroll
                for (int j = 0; j < 8; j++)
                    mma_tf32(acc[i][j], a[i], b[j]);
        }
        if (more) {
            int nb = buf ^ 1;
            #pragma unroll
            for (int q = 0; q < 4; q++) {
                uint4 u;
                u.x = f2tf(Apre[q].x); u.y = f2tf(Apre[q].y);
                u.z = f2tf(Apre[q].z); u.w = f2tf(Apre[q].w);
                *(uint4*)&As[nb][arow][q * 4] = u;
            }
            #pragma unroll
            for (int q = 0; q < 4; q++) {
                uint4 u;
                u.x = f2tf(Bpre[q].x); u.y = f2tf(Bpre[q].y);
                u.z = f2tf(Bpre[q].z); u.w = f2tf(Bpre[q].w);
                *(uint4*)&Bs[nb][bkr][bn16 + q * 4] = u;
            }
        }
        __syncthreads();
        buf ^= 1;
    }

    // epilogue: out = acc + X + bias
    #pragma unroll
    for (int i = 0; i < 4; i++) {
        #pragma unroll
        for (int j = 0; j < 8; j++) {
            int r1 = brow + m0w + 16 * i + g;
            int r2 = r1 + 8;
            int cc = bcol + n0w + 8 * j + 2 * tig;
            float2 bb = *(const float2*)(bias + cc);
            float2 x1 = *(const float2*)(X + (size_t)r1 * Dn + cc);
            float2 o1 = make_float2(acc[i][j][0] + x1.x + bb.x,
                                    acc[i][j][1] + x1.y + bb.y);
            *(float2*)(g_xnew + (size_t)r1 * Dn + cc) = o1;
            float2 x2 = *(const float2*)(X + (size_t)r2 * Dn + cc);
            float2 o2 = make_float2(acc[i][j][2] + x2.x + bb.x,
                                    acc[i][j][3] + x2.y + bb.y);
            *(float2*)(g_xnew + (size_t)r2 * Dn + cc) = o2;
        }
    }
}

// ===== scores + LN stats: 256 rows x 32 cols per block =====
__global__ void __launch_bounds__(256)
k_scores(float* __restrict__ attn_out) {
    __shared__ float Xs[32][260];   // also reused as stats-partial buffer
    __shared__ float As2[32][32];   // also reused as mean/rstd broadcast
    int t  = threadIdx.x;
    int R0 = blockIdx.x * 256;
    int rgrp = t & 31, cgrp = t >> 5;
    int r0 = rgrp * 8, c0 = cgrp * 4;

    float acc[8][4];
    float s[8], q[8];
    #pragma unroll
    for (int i = 0; i < 8; i++) {
        s[i] = 0.f; q[i] = 0.f;
        #pragma unroll
        for (int j = 0; j < 4; j++) acc[i][j] = 0.f;
    }

    for (int dt = 0; dt < 16; dt++) {
        #pragma unroll
        for (int i = 0; i < 8; i++) {
            int rr  = (t >> 3) + i * 32;
            int dd0 = (t & 7) * 4;
            float4 a4 = *(const float4*)(g_xnew + (size_t)(R0 + rr) * Dn + dt * 32 + dd0);
            Xs[dd0 + 0][rr] = a4.x;
            Xs[dd0 + 1][rr] = a4.y;
            Xs[dd0 + 2][rr] = a4.z;
            Xs[dd0 + 3][rr] = a4.w;
        }
        {
            int dp = t >> 3, c4 = (t & 7) * 4;
            *(float4*)&As2[dp][c4] = *(const float4*)(g_Ag + (dt * 32 + dp) * 32 + c4);
        }
        __syncthreads();
        #pragma unroll
        for (int dd2 = 0; dd2 < 4; dd2++) {
            int dd = cgrp * 4 + dd2;
            float4 va = *(const float4*)&Xs[dd][r0];
            float4 vb = *(const float4*)&Xs[dd][r0 + 4];
            s[0] += va.x; q[0] += va.x * va.x;
            s[1] += va.y; q[1] += va.y * va.y;
            s[2] += va.z; q[2] += va.z * va.z;
            s[3] += va.w; q[3] += va.w * va.w;
            s[4] += vb.x; q[4] += vb.x * vb.x;
            s[5] += vb.y; q[5] += vb.y * vb.y;
            s[6] += vb.z; q[6] += vb.z * vb.z;
            s[7] += vb.w; q[7] += vb.w * vb.w;
        }
        #pragma unroll
        for (int dd = 0; dd < 32; dd++) {
            float xa[8], ab[4];
            *(float4*)&xa[0] = *(const float4*)&Xs[dd][r0];
            *(float4*)&xa[4] = *(const float4*)&Xs[dd][r0 + 4];
            *(float4*)&ab[0] = *(const float4*)&As2[dd][c0];
            #pragma unroll
            for (int i = 0; i < 8; i++)
                #pragma unroll
                for (int j = 0; j < 4; j++) acc[i][j] += xa[i] * ab[j];
        }
        __syncthreads();
    }

    float* sS = &Xs[0][0];
    float* sQ = sS + 2048;
    #pragma unroll
    for (int i = 0; i < 8; i++) {
        sS[cgrp * 256 + r0 + i] = s[i];
        sQ[cgrp * 256 + r0 + i] = q[i];
    }
    __syncthreads();
    float* smM = &As2[0][0];
    float* smR = smM + 256;
    {
        float ssum = 0.f, qsum = 0.f;
        #pragma unroll
        for (int cg = 0; cg < 8; cg++) {
            ssum += sS[cg * 256 + t];
            qsum += sQ[cg * 256 + t];
        }
        float m   = ssum * (1.f / Dn);
        float var = qsum * (1.f / Dn) - m * m;
        float rs  = rsqrtf(var + 1e-5f);
        g_mean[R0 + t] = m;
        g_rstd[R0 + t] = rs;
        smM[t] = m;
        smR[t] = rs;
    }
    __syncthreads();

    #pragma unroll
    for (int i = 0; i < 8; i++) {
        int rl = r0 + i;
        int gr = R0 + rl;
        float rs = smR[rl], mn = smM[rl];
        int b = gr >> 11, sidx = gr & 2047;
        #pragma unroll
        for (int j = 0; j < 4; j++) {
            int c = c0 + j;
            float sc = rs * (acc[i][j] - mn * g_GA[c]) + g_BA[c]
                       - 7.6246189861593985f;
            float a = 1.f / (1.f + expf(-sc));
            attn_out[((size_t)(b * 32 + c)) * Sn + sidx] = a;
        }
    }
}

// ===== z + fused P,Q =====
__global__ void __launch_bounds__(256)
k_zpq(const float* __restrict__ attn) {
    __shared__ float a_sm[32][36];
    int t  = threadIdx.x;
    int d0 = blockIdx.x * 128;
    int b  = blockIdx.y;
    int cq = t >> 5;
    int dq = t & 31;
    int c0 = cq * 4;
    int d  = d0 + dq * 4;
    bool dopq = (blockIdx.x == 0);

    float acc[4][4];
    #pragma unroll
    for (int j = 0; j < 4; j++)
        #pragma unroll
        for (int k = 0; k < 4; k++) acc[j][k] = 0.f;
    float Pl = 0.f, Ql = 0.f;

    int lc  = t >> 3;
    int ls4 = (t & 7) * 4;
    for (int s0 = 0; s0 < Sn; s0 += 32) {
        {
            float4 a4 = *(const float4*)(attn + ((size_t)(b * 32 + lc)) * Sn + s0 + ls4);
            float4 r4 = *(const float4*)(g_rstd + b * Sn + s0 + ls4);
            if (dopq) {
                float4 m4 = *(const float4*)(g_mean + b * Sn + s0 + ls4);
                Pl += a4.x + a4.y + a4.z + a4.w;
                Ql += a4.x * r4.x * m4.x + a4.y * r4.y * m4.y
                    + a4.z * r4.z * m4.z + a4.w * r4.w * m4.w;
            }
            a4.x *= r4.x; a4.y *= r4.y; a4.z *= r4.z; a4.w *= r4.w;
            *(float4*)&a_sm[lc][ls4] = a4;
        }
        __syncthreads();
        #pragma unroll 8
        for (int si = 0; si < 32; si++) {
            float4 xv = *(const float4*)(g_xnew + (size_t)(b * Sn + s0 + si) * Dn + d);
            #pragma unroll
            for (int j = 0; j < 4; j++) {
                float av = a_sm[c0 + j][si];
                acc[j][0] += av * xv.x;
                acc[j][1] += av * xv.y;
                acc[j][2] += av * xv.z;
                acc[j][3] += av * xv.w;
            }
        }
        __syncthreads();
    }
    #pragma unroll
    for (int j = 0; j < 4; j++) {
        float4 o4 = make_float4(acc[j][0], acc[j][1], acc[j][2], acc[j][3]);
        *(float4*)(g_z + (size_t)(b * 32 + c0 + j) * Dn + d) = o4;
    }
    if (dopq) {
        Pl += __shfl_down_sync(0xffffffffu, Pl, 4, 8);
        Pl += __shfl_down_sync(0xffffffffu, Pl, 2, 8);
        Pl += __shfl_down_sync(0xffffffffu, Pl, 1, 8);
        Ql += __shfl_down_sync(0xffffffffu, Ql, 4, 8);
        Ql += __shfl_down_sync(0xffffffffu, Ql, 2, 8);
        Ql += __shfl_down_sync(0xffffffffu, Ql, 1, 8);
        if ((t & 7) == 0) {
            g_P[b * 32 + lc] = Pl;
            g_Q[b * 32 + lc] = Ql;
        }
    }
}

// ===== fused o + head: per (b,n) block =====
__global__ void __launch_bounds__(256)
k_ohead(const float* __restrict__ Wkv, const float* __restrict__ g1,
        const float* __restrict__ Wproj, const float* __restrict__ bproj,
        const float* __restrict__ g2, const float* __restrict__ b2,
        const float* __restrict__ Wc1, const float* __restrict__ bc1,
        const float* __restrict__ Wc2, const float* __restrict__ bc2,
        float* __restrict__ out) {
    __shared__ float zs[16][512];
    __shared__ float row[Dn];
    __shared__ float tmp[Dn];
    __shared__ float red[256];
    __shared__ float sg1[Dn];
    int b = blockIdx.x, n = blockIdx.y;
    int t = threadIdx.x;
    int hh = t >> 5;
    int hd = t & 31;

    sg1[t] = g1[t];
    sg1[t + 256] = g1[t + 256];
    __syncthreads();
    for (int idx = t; idx < 16 * 512; idx += 256) {
        int h = idx >> 9, d = idx & 511;
        zs[h][d] = g_z[(size_t)(b * 32 + h * 2 + n) * Dn + d] * sg1[d];
    }
    __syncthreads();

    #pragma unroll
    for (int hi = 0; hi < 2; hi++) {
        int h = hh + hi * 8;
        int j = h * HDn + hd;
        float acc = 0.f;
        for (int d = 0; d < Dn; d++)
            acc += zs[h][d] * Wkv[(size_t)d * (2 * Dn) + Dn + j];
        int c = h * 2 + n;
        row[j] = acc - g_Q[b * 32 + c] * g_Gv[j] + g_P[b * 32 + c] * g_Bv[j];
    }
    __syncthreads();

    float a0 = 0.f, a1 = 0.f;
    for (int d = 0; d < Dn; d++) {
        float rv = row[d];
        a0 += rv * Wproj[d * Dn + t];
        a1 += rv * Wproj[d * Dn + t + 256];
    }
    tmp[t]       = a0 + bproj[t];
    tmp[t + 256] = a1 + bproj[t + 256];
    __syncthreads();

    float ps  = tmp[t] + tmp[t + 256];
    float pss = tmp[t] * tmp[t] + tmp[t + 256] * tmp[t + 256];
    red[t] = ps; __syncthreads();
    for (int o = 128; o > 0; o >>= 1) { if (t < o) red[t] += red[t + o]; __syncthreads(); }
    float mean = red[0] * (1.f / Dn);
    __syncthreads();
    red[t] = pss; __syncthreads();
    for (int o = 128; o > 0; o >>= 1) { if (t < o) red[t] += red[t + o]; __syncthreads(); }
    float var  = red[0] * (1.f / Dn) - mean * mean;
    float rstd = rsqrtf(var + 1e-5f);
    __syncthreads();

    row[t]       = (tmp[t] - mean) * rstd * g2[t] + b2[t];
    row[t + 256] = (tmp[t + 256] - mean) * rstd * g2[t + 256] + b2[t + 256];
    __syncthreads();

    float c0 = 0.f, c1 = 0.f;
    for (int d = 0; d < Dn; d++) {
        float rv = row[d];
        c0 += rv * Wc1[d * Dn + t];
        c1 += rv * Wc1[d * Dn + t + 256];
    }
    c0 = fmaxf(c0 + bc1[t], 0.f);
    c1 = fmaxf(c1 + bc1[t + 256], 0.f);
    float part = c0 * Wc2[t] + c1 * Wc2[t + 256];
    red[t] = part; __syncthreads();
    for (int o = 128; o > 0; o >>= 1) { if (t < o) red[t] += red[t + o]; __syncthreads(); }
    if (t == 0) out[b * NCLSn + n] = red[0] + bc2[0];
}

// ===== launch =====
extern "C" void kernel_launch(void* const* d_in, const int* in_sizes, int n_in,
                              void* d_out, int out_size) {
    const float* x     = (const float*)d_in[0];
    const float* wave1 = (const float*)d_in[1];
    const float* wave2 = (const float*)d_in[2];
    const float* wave3 = (const float*)d_in[3];
    const float* Wp1   = (const float*)d_in[4];
    const float* bp1   = (const float*)d_in[5];
    const float* cls   = (const float*)d_in[6];
    const float* ln1g  = (const float*)d_in[7];
    const float* ln1b  = (const float*)d_in[8];
    const float* Wq    = (const float*)d_in[9];
    const float* Wkv   = (const float*)d_in[10];
    const float* Wproj = (const float*)d_in[11];
    const float* bproj = (const float*)d_in[12];
    const float* ln2g  = (const float*)d_in[13];
    const float* ln2b  = (const float*)d_in[14];
    const float* Wc1   = (const float*)d_in[15];
    const float* bc1   = (const float*)d_in[16];
    const float* Wc2   = (const float*)d_in[17];
    const float* bc2   = (const float*)d_in[18];
    float* out = (float*)d_out;
    float* attn = out + Bn * NCLSn;

    k_prep_ksum<<<1, 512>>>(wave1, wave2, wave3);                 // 1
    k_prep_qA<<<1, 1024>>>(cls, Wq, Wkv, ln1g, ln1b);             // 2
    k_prep_vvec<<<4, 128>>>(Wkv, ln1g, ln1b);                     // 3
    k_conv<<<Rn / 16, 512>>>(x);                                  // 4  <- profiled
    k_gemm0<<<dim3(4, 512), 128>>>(Wp1, x, bp1);                  // 5
    k_scores<<<256, 256>>>(attn);                                 // 6
    k_zpq<<<dim3(4, Bn), 256>>>(attn);                            // 7
    k_ohead<<<dim3(Bn, NCLSn), 256>>>(Wkv, ln1g, Wproj, bproj,
                                      ln2g, ln2b, Wc1, bc1, Wc2, bc2, out); // 8
}

// round 9
// speedup vs baseline: 1.2072x; 1.1327x over previous
#include <cuda_runtime.h>
#include <math.h>

// ===== problem constants =====
#define Bn    32
#define Sn    2048
#define Dn    512
#define NCLSn 2
#define Hn    16
#define HDn   32
#define Rn    (Bn*Sn)      // 65536 rows
#define KS    19

// ===== scratch =====
__device__ float g_kT[KS*Dn];
__device__ float g_Ag[Dn*32];
__device__ float g_GA[32];
__device__ float g_BA[32];
__device__ float g_Gv[Dn];
__device__ float g_Bv[Dn];
__device__ float g_pos[Rn*Dn];         // 128 MB
__device__ float g_xnew[Rn*Dn];        // 128 MB
__device__ float g_mean[Rn];
__device__ float g_rstd[Rn];
__device__ float g_z[Bn*32*Dn];        // 2 MB
__device__ float g_P[Bn*32];
__device__ float g_Q[Bn*32];

// ===== tf32 helpers =====
__device__ __forceinline__ unsigned f2tf(float x) {
    unsigned u;
    asm("cvt.rna.tf32.f32 %0, %1;" : "=r"(u) : "f"(x));
    return u;
}
__device__ __forceinline__ void mma_tf32(float* c, const unsigned* a, const unsigned* b) {
    asm volatile(
        "mma.sync.aligned.m16n8k8.row.col.f32.tf32.tf32.f32 "
        "{%0,%1,%2,%3},{%4,%5,%6,%7},{%8,%9},{%0,%1,%2,%3};"
        : "+f"(c[0]), "+f"(c[1]), "+f"(c[2]), "+f"(c[3])
        : "r"(a[0]), "r"(a[1]), "r"(a[2]), "r"(a[3]), "r"(b[0]), "r"(b[1]));
}

// ===== prep A: block 0 = summed mexican-hat kernel; block 1 = Gv/Bv =====
__global__ void __launch_bounds__(512)
k_prep_small(const float* __restrict__ w1, const float* __restrict__ w2,
             const float* __restrict__ w3, const float* __restrict__ Wkv,
             const float* __restrict__ g1, const float* __restrict__ b1) {
    int t = threadIdx.x;
    if (blockIdx.x == 0) {
        int d = t;
        const float C = 0.8673250705840776f;
        float out[KS];
        #pragma unroll
        for (int j = 0; j < KS; j++) out[j] = 0.f;
        const float* ws[3] = {w1, w2, w3};
        for (int w = 0; w < 3; w++) {
            float scale = ws[w][d];
            float shift = ws[w][Dn + d];
            float inv   = 1.f / scale;
            float amp   = C * rsqrtf(fabsf(scale));
            #pragma unroll
            for (int j = 0; j < KS; j++) {
                float xg = (float)(j - 9) - shift;
                float u  = xg * inv;
                out[j] += amp * (1.f - u * u) * expf(-0.5f * u * u);
            }
        }
        #pragma unroll
        for (int j = 0; j < KS; j++) g_kT[j * Dn + d] = out[j];
    } else {
        int j = t;
        float gv = 0.f, bv = 0.f;
        #pragma unroll 8
        for (int d = 0; d < Dn; d++) {
            float w = Wkv[(size_t)d * (2 * Dn) + Dn + j];
            gv += g1[d] * w;
            bv += b1[d] * w;
        }
        g_Gv[j] = gv;
        g_Bv[j] = bv;
    }
}

// ===== merged prep: q = cls@Wq; Ag; GA; BA =====
__global__ void __launch_bounds__(1024)
k_prep_qA(const float* __restrict__ cls, const float* __restrict__ Wq,
          const float* __restrict__ Wkv, const float* __restrict__ g1,
          const float* __restrict__ b1) {
    __shared__ float sq[NCLSn * Dn];
    __shared__ float ra[32][33];
    __shared__ float rb[32][33];
    int t = threadIdx.x;
    {
        int n = t >> 9, dp = t & 511;
        float acc = 0.f;
        #pragma unroll 8
        for (int d = 0; d < Dn; d++)
            acc += cls[n * Dn + d] * Wq[d * Dn + dp];
        sq[n * Dn + dp] = acc;
    }
    __syncthreads();
    int c = t & 31;
    int h = c >> 1, n = c & 1;
    int dg = t >> 5;
    float ga = 0.f, ba = 0.f;
    #pragma unroll
    for (int p = 0; p < 16; p++) {
        int d = dg + p * 32;
        float acc = 0.f;
        #pragma unroll
        for (int hd = 0; hd < HDn; hd++)
            acc += Wkv[(size_t)d * (2 * Dn) + h * HDn + hd] * sq[n * Dn + h * HDn + hd];
        acc *= 0.17677669529663687f;
        float ag = g1[d] * acc;
        g_Ag[d * 32 + c] = ag;
        ga += ag;
        ba += b1[d] * acc;
    }
    ra[dg][c] = ga;
    rb[dg][c] = ba;
    __syncthreads();
    if (t < 32) {
        float sga = 0.f, sba = 0.f;
        #pragma unroll
        for (int k = 0; k < 32; k++) { sga += ra[k][t]; sba += rb[k][t]; }
        g_GA[t] = sga;
        g_BA[t] = sba;
    }
}

// ===== depthwise conv: 16 outputs/thread =====
__global__ void __launch_bounds__(512)
k_conv(const float* __restrict__ x) {
    int chunk = blockIdx.x;
    int b  = chunk >> 7;
    int s0 = (chunk & 127) * 16;
    int d  = threadIdx.x;
    const float* xb = x + (size_t)b * Sn * Dn;

    float w[KS];
    #pragma unroll
    for (int j = 0; j < KS; j++) w[j] = g_kT[j * Dn + d];

    float xv[34];
    #pragma unroll
    for (int l = 0; l < 34; l++) {
        int ss = s0 - 9 + l;
        xv[l] = ((unsigned)ss < (unsigned)Sn) ? xb[(size_t)ss * Dn + d] : 0.f;
    }
    float* pb = g_pos + ((size_t)(b * Sn + s0)) * Dn + d;
    #pragma unroll
    for (int o = 0; o < 16; o++) {
        float acc = 0.f;
        #pragma unroll
        for (int j = 0; j < KS; j++) acc += xv[o + j] * w[j];
        pb[(size_t)o * Dn] = acc;
    }
}

// ===== GEMM0 (tf32 TC): xnew = pos @ Wp1 + x + bp1 =====
// PROVEN config: 128x128 block tile, 8 warps (64x32 warp tiles), K-tile 16.
// As [m][k] pad-20; Bs [k][n] pad-136. No LN epilogue (scores computes stats).
#define APAD 20
#define BPAD 136
__global__ void __launch_bounds__(256)
k_gemm0(const float* __restrict__ Wp1, const float* __restrict__ X,
        const float* __restrict__ bias) {
    __shared__ unsigned As[2][128][APAD];   // [m][k]
    __shared__ unsigned Bs[2][16][BPAD];    // [k][n]
    int t    = threadIdx.x;
    int brow = blockIdx.y * 128;
    int bcol = blockIdx.x * 128;
    int lane = t & 31, warp = t >> 5;
    int g    = lane >> 2, tig = lane & 3;
    int m0w  = (warp >> 2) * 64;
    int n0w  = (warp & 3) * 32;

    int arow = t >> 1, akh = (t & 1) * 8;
    int bkr  = t >> 4, bn8 = (t & 15) * 8;

    const float* pA = g_pos + (size_t)(brow + arow) * Dn + akh;
    const float* pB = Wp1 + (size_t)bkr * Dn + bcol + bn8;

    float acc[4][4][4];
    #pragma unroll
    for (int i = 0; i < 4; i++)
        #pragma unroll
        for (int j = 0; j < 4; j++)
            #pragma unroll
            for (int k = 0; k < 4; k++) acc[i][j][k] = 0.f;

    {
        float4 A0 = *(const float4*)(pA);
        float4 A1 = *(const float4*)(pA + 4);
        float4 B0 = *(const float4*)(pB);
        float4 B1 = *(const float4*)(pB + 4);
        uint4 u;
        u.x = f2tf(A0.x); u.y = f2tf(A0.y); u.z = f2tf(A0.z); u.w = f2tf(A0.w);
        *(uint4*)&As[0][arow][akh] = u;
        u.x = f2tf(A1.x); u.y = f2tf(A1.y); u.z = f2tf(A1.z); u.w = f2tf(A1.w);
        *(uint4*)&As[0][arow][akh + 4] = u;
        u.x = f2tf(B0.x); u.y = f2tf(B0.y); u.z = f2tf(B0.z); u.w = f2tf(B0.w);
        *(uint4*)&Bs[0][bkr][bn8] = u;
        u.x = f2tf(B1.x); u.y = f2tf(B1.y); u.z = f2tf(B1.z); u.w = f2tf(B1.w);
        *(uint4*)&Bs[0][bkr][bn8 + 4] = u;
    }
    __syncthreads();

    int buf = 0;
    for (int kt = 1; kt <= 32; kt++) {
        bool more = (kt < 32);
        float4 A0, A1, B0, B1;
        if (more) {
            int k0 = kt * 16;
            A0 = *(const float4*)(pA + k0);
            A1 = *(const float4*)(pA + k0 + 4);
            B0 = *(const float4*)(pB + (size_t)k0 * Dn);
            B1 = *(const float4*)(pB + (size_t)k0 * Dn + 4);
        }
        #pragma unroll
        for (int ks = 0; ks < 16; ks += 8) {
            unsigned a[4][4], b[4][2];
            #pragma unroll
            for (int i = 0; i < 4; i++) {
                int m = m0w + 16 * i + g;
                a[i][0] = As[buf][m][ks + tig];
                a[i][1] = As[buf][m + 8][ks + tig];
                a[i][2] = As[buf][m][ks + tig + 4];
                a[i][3] = As[buf][m + 8][ks + tig + 4];
            }
            #pragma unroll
            for (int j = 0; j < 4; j++) {
                int n = n0w + 8 * j + g;
                b[j][0] = Bs[buf][ks + tig][n];
                b[j][1] = Bs[buf][ks + tig + 4][n];
            }
            #pragma unroll
            for (int i = 0; i < 4; i++)
                #pragma unroll
                for (int j = 0; j < 4; j++)
                    mma_tf32(acc[i][j], a[i], b[j]);
        }
        if (more) {
            int nb = buf ^ 1;
            uint4 u;
            u.x = f2tf(A0.x); u.y = f2tf(A0.y); u.z = f2tf(A0.z); u.w = f2tf(A0.w);
            *(uint4*)&As[nb][arow][akh] = u;
            u.x = f2tf(A1.x); u.y = f2tf(A1.y); u.z = f2tf(A1.z); u.w = f2tf(A1.w);
            *(uint4*)&As[nb][arow][akh + 4] = u;
            u.x = f2tf(B0.x); u.y = f2tf(B0.y); u.z = f2tf(B0.z); u.w = f2tf(B0.w);
            *(uint4*)&Bs[nb][bkr][bn8] = u;
            u.x = f2tf(B1.x); u.y = f2tf(B1.y); u.z = f2tf(B1.z); u.w = f2tf(B1.w);
            *(uint4*)&Bs[nb][bkr][bn8 + 4] = u;
        }
        __syncthreads();
        buf ^= 1;
    }

    // epilogue: out = acc + X + bias
    #pragma unroll
    for (int i = 0; i < 4; i++) {
        #pragma unroll
        for (int j = 0; j < 4; j++) {
            int r1 = brow + m0w + 16 * i + g;
            int r2 = r1 + 8;
            int cc = bcol + n0w + 8 * j + 2 * tig;
            float2 bb = *(const float2*)(bias + cc);
            float2 x1 = *(const float2*)(X + (size_t)r1 * Dn + cc);
            float2 o1 = make_float2(acc[i][j][0] + x1.x + bb.x,
                                    acc[i][j][1] + x1.y + bb.y);
            *(float2*)(g_xnew + (size_t)r1 * Dn + cc) = o1;
            float2 x2 = *(const float2*)(X + (size_t)r2 * Dn + cc);
            float2 o2 = make_float2(acc[i][j][2] + x2.x + bb.x,
                                    acc[i][j][3] + x2.y + bb.y);
            *(float2*)(g_xnew + (size_t)r2 * Dn + cc) = o2;
        }
    }
}

// ===== scores + LN stats: 256 rows x 32 cols per block =====
__global__ void __launch_bounds__(256)
k_scores(float* __restrict__ attn_out) {
    __shared__ float Xs[32][260];
    __shared__ float As2[32][32];
    int t  = threadIdx.x;
    int R0 = blockIdx.x * 256;
    int rgrp = t & 31, cgrp = t >> 5;
    int r0 = rgrp * 8, c0 = cgrp * 4;

    float acc[8][4];
    float s[8], q[8];
    #pragma unroll
    for (int i = 0; i < 8; i++) {
        s[i] = 0.f; q[i] = 0.f;
        #pragma unroll
        for (int j = 0; j < 4; j++) acc[i][j] = 0.f;
    }

    for (int dt = 0; dt < 16; dt++) {
        #pragma unroll
        for (int i = 0; i < 8; i++) {
            int rr  = (t >> 3) + i * 32;
            int dd0 = (t & 7) * 4;
            float4 a4 = *(const float4*)(g_xnew + (size_t)(R0 + rr) * Dn + dt * 32 + dd0);
            Xs[dd0 + 0][rr] = a4.x;
            Xs[dd0 + 1][rr] = a4.y;
            Xs[dd0 + 2][rr] = a4.z;
            Xs[dd0 + 3][rr] = a4.w;
        }
        {
            int dp = t >> 3, c4 = (t & 7) * 4;
            *(float4*)&As2[dp][c4] = *(const float4*)(g_Ag + (dt * 32 + dp) * 32 + c4);
        }
        __syncthreads();
        #pragma unroll
        for (int dd2 = 0; dd2 < 4; dd2++) {
            int dd = cgrp * 4 + dd2;
            float4 va = *(const float4*)&Xs[dd][r0];
            float4 vb = *(const float4*)&Xs[dd][r0 + 4];
            s[0] += va.x; q[0] += va.x * va.x;
            s[1] += va.y; q[1] += va.y * va.y;
            s[2] += va.z; q[2] += va.z * va.z;
            s[3] += va.w; q[3] += va.w * va.w;
            s[4] += vb.x; q[4] += vb.x * vb.x;
            s[5] += vb.y; q[5] += vb.y * vb.y;
            s[6] += vb.z; q[6] += vb.z * vb.z;
            s[7] += vb.w; q[7] += vb.w * vb.w;
        }
        #pragma unroll
        for (int dd = 0; dd < 32; dd++) {
            float xa[8], ab[4];
            *(float4*)&xa[0] = *(const float4*)&Xs[dd][r0];
            *(float4*)&xa[4] = *(const float4*)&Xs[dd][r0 + 4];
            *(float4*)&ab[0] = *(const float4*)&As2[dd][c0];
            #pragma unroll
            for (int i = 0; i < 8; i++)
                #pragma unroll
                for (int j = 0; j < 4; j++) acc[i][j] += xa[i] * ab[j];
        }
        __syncthreads();
    }

    float* sS = &Xs[0][0];
    float* sQ = sS + 2048;
    #pragma unroll
    for (int i = 0; i < 8; i++) {
        sS[cgrp * 256 + r0 + i] = s[i];
        sQ[cgrp * 256 + r0 + i] = q[i];
    }
    __syncthreads();
    float* smM = &As2[0][0];
    float* smR = smM + 256;
    {
        float ssum = 0.f, qsum = 0.f;
        #pragma unroll
        for (int cg = 0; cg < 8; cg++) {
            ssum += sS[cg * 256 + t];
            qsum += sQ[cg * 256 + t];
        }
        float m   = ssum * (1.f / Dn);
        float var = qsum * (1.f / Dn) - m * m;
        float rs  = rsqrtf(var + 1e-5f);
        g_mean[R0 + t] = m;
        g_rstd[R0 + t] = rs;
        smM[t] = m;
        smR[t] = rs;
    }
    __syncthreads();

    #pragma unroll
    for (int i = 0; i < 8; i++) {
        int rl = r0 + i;
        int gr = R0 + rl;
        float rs = smR[rl], mn = smM[rl];
        int b = gr >> 11, sidx = gr & 2047;
        #pragma unroll
        for (int j = 0; j < 4; j++) {
            int c = c0 + j;
            float sc = rs * (acc[i][j] - mn * g_GA[c]) + g_BA[c]
                       - 7.6246189861593985f;
            float a = 1.f / (1.f + expf(-sc));
            attn_out[((size_t)(b * 32 + c)) * Sn + sidx] = a;
        }
    }
}

// ===== z + fused P,Q =====
__global__ void __launch_bounds__(256)
k_zpq(const float* __restrict__ attn) {
    __shared__ float a_sm[32][36];
    int t  = threadIdx.x;
    int d0 = blockIdx.x * 128;
    int b  = blockIdx.y;
    int cq = t >> 5;
    int dq = t & 31;
    int c0 = cq * 4;
    int d  = d0 + dq * 4;
    bool dopq = (blockIdx.x == 0);

    float acc[4][4];
    #pragma unroll
    for (int j = 0; j < 4; j++)
        #pragma unroll
        for (int k = 0; k < 4; k++) acc[j][k] = 0.f;
    float Pl = 0.f, Ql = 0.f;

    int lc  = t >> 3;
    int ls4 = (t & 7) * 4;
    for (int s0 = 0; s0 < Sn; s0 += 32) {
        {
            float4 a4 = *(const float4*)(attn + ((size_t)(b * 32 + lc)) * Sn + s0 + ls4);
            float4 r4 = *(const float4*)(g_rstd + b * Sn + s0 + ls4);
            if (dopq) {
                float4 m4 = *(const float4*)(g_mean + b * Sn + s0 + ls4);
                Pl += a4.x + a4.y + a4.z + a4.w;
                Ql += a4.x * r4.x * m4.x + a4.y * r4.y * m4.y
                    + a4.z * r4.z * m4.z + a4.w * r4.w * m4.w;
            }
            a4.x *= r4.x; a4.y *= r4.y; a4.z *= r4.z; a4.w *= r4.w;
            *(float4*)&a_sm[lc][ls4] = a4;
        }
        __syncthreads();
        #pragma unroll 8
        for (int si = 0; si < 32; si++) {
            float4 xv = *(const float4*)(g_xnew + (size_t)(b * Sn + s0 + si) * Dn + d);
            #pragma unroll
            for (int j = 0; j < 4; j++) {
                float av = a_sm[c0 + j][si];
                acc[j][0] += av * xv.x;
                acc[j][1] += av * xv.y;
                acc[j][2] += av * xv.z;
                acc[j][3] += av * xv.w;
            }
        }
        __syncthreads();
    }
    #pragma unroll
    for (int j = 0; j < 4; j++) {
        float4 o4 = make_float4(acc[j][0], acc[j][1], acc[j][2], acc[j][3]);
        *(float4*)(g_z + (size_t)(b * 32 + c0 + j) * Dn + d) = o4;
    }
    if (dopq) {
        Pl += __shfl_down_sync(0xffffffffu, Pl, 4, 8);
        Pl += __shfl_down_sync(0xffffffffu, Pl, 2, 8);
        Pl += __shfl_down_sync(0xffffffffu, Pl, 1, 8);
        Ql += __shfl_down_sync(0xffffffffu, Ql, 4, 8);
        Ql += __shfl_down_sync(0xffffffffu, Ql, 2, 8);
        Ql += __shfl_down_sync(0xffffffffu, Ql, 1, 8);
        if ((t & 7) == 0) {
            g_P[b * 32 + lc] = Pl;
            g_Q[b * 32 + lc] = Ql;
        }
    }
}

// ===== fused o + head: per (b,n) block =====
__global__ void __launch_bounds__(256)
k_ohead(const float* __restrict__ Wkv, const float* __restrict__ g1,
        const float* __restrict__ Wproj, const float* __restrict__ bproj,
        const float* __restrict__ g2, const float* __restrict__ b2,
        const float* __restrict__ Wc1, const float* __restrict__ bc1,
        const float* __restrict__ Wc2, const float* __restrict__ bc2,
        float* __restrict__ out) {
    __shared__ float zs[16][512];
    __shared__ float row[Dn];
    __shared__ float tmp[Dn];
    __shared__ float red[256];
    __shared__ float sg1[Dn];
    int b = blockIdx.x, n = blockIdx.y;
    int t = threadIdx.x;
    int hh = t >> 5;
    int hd = t & 31;

    sg1[t] = g1[t];
    sg1[t + 256] = g1[t + 256];
    __syncthreads();
    for (int idx = t; idx < 16 * 512; idx += 256) {
        int h = idx >> 9, d = idx & 511;
        zs[h][d] = g_z[(size_t)(b * 32 + h * 2 + n) * Dn + d] * sg1[d];
    }
    __syncthreads();

    #pragma unroll
    for (int hi = 0; hi < 2; hi++) {
        int h = hh + hi * 8;
        int j = h * HDn + hd;
        float acc = 0.f;
        for (int d = 0; d < Dn; d++)
            acc += zs[h][d] * Wkv[(size_t)d * (2 * Dn) + Dn + j];
        int c = h * 2 + n;
        row[j] = acc - g_Q[b * 32 + c] * g_Gv[j] + g_P[b * 32 + c] * g_Bv[j];
    }
    __syncthreads();

    float a0 = 0.f, a1 = 0.f;
    for (int d = 0; d < Dn; d++) {
        float rv = row[d];
        a0 += rv * Wproj[d * Dn + t];
        a1 += rv * Wproj[d * Dn + t + 256];
    }
    tmp[t]       = a0 + bproj[t];
    tmp[t + 256] = a1 + bproj[t + 256];
    __syncthreads();

    float ps  = tmp[t] + tmp[t + 256];
    float pss = tmp[t] * tmp[t] + tmp[t + 256] * tmp[t + 256];
    red[t] = ps; __syncthreads();
    for (int o = 128; o > 0; o >>= 1) { if (t < o) red[t] += red[t + o]; __syncthreads(); }
    float mean = red[0] * (1.f / Dn);
    __syncthreads();
    red[t] = pss; __syncthreads();
    for (int o = 128; o > 0; o >>= 1) { if (t < o) red[t] += red[t + o]; __syncthreads(); }
    float var  = red[0] * (1.f / Dn) - mean * mean;
    float rstd = rsqrtf(var + 1e-5f);
    __syncthreads();

    row[t]       = (tmp[t] - mean) * rstd * g2[t] + b2[t];
    row[t + 256] = (tmp[t + 256] - mean) * rstd * g2[t + 256] + b2[t + 256];
    __syncthreads();

    float c0 = 0.f, c1 = 0.f;
    for (int d = 0; d < Dn; d++) {
        float rv = row[d];
        c0 += rv * Wc1[d * Dn + t];
        c1 += rv * Wc1[d * Dn + t + 256];
    }
    c0 = fmaxf(c0 + bc1[t], 0.f);
    c1 = fmaxf(c1 + bc1[t + 256], 0.f);
    float part = c0 * Wc2[t] + c1 * Wc2[t + 256];
    red[t] = part; __syncthreads();
    for (int o = 128; o > 0; o >>= 1) { if (t < o) red[t] += red[t + o]; __syncthreads(); }
    if (t == 0) out[b * NCLSn + n] = red[0] + bc2[0];
}

// ===== launch =====
extern "C" void kernel_launch(void* const* d_in, const int* in_sizes, int n_in,
                              void* d_out, int out_size) {
    const float* x     = (const float*)d_in[0];
    const float* wave1 = (const float*)d_in[1];
    const float* wave2 = (const float*)d_in[2];
    const float* wave3 = (const float*)d_in[3];
    const float* Wp1   = (const float*)d_in[4];
    const float* bp1   = (const float*)d_in[5];
    const float* cls   = (const float*)d_in[6];
    const float* ln1g  = (const float*)d_in[7];
    const float* ln1b  = (const float*)d_in[8];
    const float* Wq    = (const float*)d_in[9];
    const float* Wkv   = (const float*)d_in[10];
    const float* Wproj = (const float*)d_in[11];
    const float* bproj = (const float*)d_in[12];
    const float* ln2g  = (const float*)d_in[13];
    const float* ln2b  = (const float*)d_in[14];
    const float* Wc1   = (const float*)d_in[15];
    const float* bc1   = (const float*)d_in[16];
    const float* Wc2   = (const float*)d_in[17];
    const float* bc2   = (const float*)d_in[18];
    float* out = (float*)d_out;
    float* attn = out + Bn * NCLSn;

    k_prep_small<<<2, 512>>>(wave1, wave2, wave3, Wkv, ln1g, ln1b);  // 1
    k_prep_qA<<<1, 1024>>>(cls, Wq, Wkv, ln1g, ln1b);                // 2
    k_conv<<<Rn / 16, 512>>>(x);                                     // 3
    k_gemm0<<<dim3(4, 512), 256>>>(Wp1, x, bp1);                     // 4  <- profiled
    k_scores<<<256, 256>>>(attn);                                    // 5
    k_zpq<<<dim3(4, Bn), 256>>>(attn);                               // 6
    k_ohead<<<dim3(Bn, NCLSn), 256>>>(Wkv, ln1g, Wproj, bproj,
                                      ln2g, ln2b, Wc1, bc1, Wc2, bc2, out); // 7
}

// round 10
// speedup vs baseline: 1.5847x; 1.3127x over previous
#include <cuda_runtime.h>
#include <math.h>

// ===== problem constants =====
#define Bn    32
#define Sn    2048
#define Dn    512
#define NCLSn 2
#define Hn    16
#define HDn   32
#define Rn    (Bn*Sn)      // 65536 rows
#define KS    19

// ===== scratch =====
__device__ float    g_kT[KS*Dn];
__device__ float    g_Ag[Dn*32];
__device__ float    g_GA[32];
__device__ float    g_BA[32];
__device__ float    g_Gv[Dn];
__device__ float    g_Bv[Dn];
__device__ unsigned g_Wp1t[Dn*Dn];     // tf32-converted Wp1
__device__ float    g_pos[Rn*Dn];      // 128 MB (tf32-rounded values)
__device__ float    g_xnew[Rn*Dn];     // 128 MB
__device__ float    g_mean[Rn];
__device__ float    g_rstd[Rn];
__device__ float    g_zp[4*Bn*32*Dn];  // 8 MB, partial z per s-chunk
__device__ float    g_Pp[4*Bn*32];
__device__ float    g_Qp[4*Bn*32];

// ===== tf32 helpers =====
__device__ __forceinline__ unsigned f2tf(float x) {
    unsigned u;
    asm("cvt.rna.tf32.f32 %0, %1;" : "=r"(u) : "f"(x));
    return u;
}
__device__ __forceinline__ void mma_tf32(float* c, const unsigned* a, const unsigned* b) {
    asm volatile(
        "mma.sync.aligned.m16n8k8.row.col.f32.tf32.tf32.f32 "
        "{%0,%1,%2,%3},{%4,%5,%6,%7},{%8,%9},{%0,%1,%2,%3};"
        : "+f"(c[0]), "+f"(c[1]), "+f"(c[2]), "+f"(c[3])
        : "r"(a[0]), "r"(a[1]), "r"(a[2]), "r"(a[3]), "r"(b[0]), "r"(b[1]));
}

// ===== tiny: summed mexican-hat kernel =====
__global__ void __launch_bounds__(512)
k_ksum(const float* __restrict__ w1, const float* __restrict__ w2,
       const float* __restrict__ w3) {
    int d = threadIdx.x;
    const float C = 0.8673250705840776f;
    float out[KS];
    #pragma unroll
    for (int j = 0; j < KS; j++) out[j] = 0.f;
    const float* ws[3] = {w1, w2, w3};
    for (int w = 0; w < 3; w++) {
        float scale = ws[w][d];
        float shift = ws[w][Dn + d];
        float inv   = 1.f / scale;
        float amp   = C * rsqrtf(fabsf(scale));
        #pragma unroll
        for (int j = 0; j < KS; j++) {
            float xg = (float)(j - 9) - shift;
            float u  = xg * inv;
            out[j] += amp * (1.f - u * u) * expf(-0.5f * u * u);
        }
    }
    #pragma unroll
    for (int j = 0; j < KS; j++) g_kT[j * Dn + d] = out[j];
}

// ===== mega: conv (blocks 0..4095) + GvBv (4096) + qA (4097) + Wp1cvt (4098..4105) =====
__global__ void __launch_bounds__(512)
k_mega(const float* __restrict__ x, const float* __restrict__ Wkv,
       const float* __restrict__ g1, const float* __restrict__ b1,
       const float* __restrict__ cls, const float* __restrict__ Wq,
       const float* __restrict__ Wp1) {
    __shared__ float sq[NCLSn * Dn];
    __shared__ float ra[16][33];
    __shared__ float rb[16][33];
    int t = threadIdx.x;
    int blk = blockIdx.x;

    if (blk < 4096) {
        // ---- depthwise conv, 16 outputs/thread; store tf32-rounded ----
        int b  = blk >> 7;
        int s0 = (blk & 127) * 16;
        int d  = t;
        const float* xb = x + (size_t)b * Sn * Dn;
        float w[KS];
        #pragma unroll
        for (int j = 0; j < KS; j++) w[j] = g_kT[j * Dn + d];
        float xv[34];
        #pragma unroll
        for (int l = 0; l < 34; l++) {
            int ss = s0 - 9 + l;
            xv[l] = ((unsigned)ss < (unsigned)Sn) ? xb[(size_t)ss * Dn + d] : 0.f;
        }
        float* pb = g_pos + ((size_t)(b * Sn + s0)) * Dn + d;
        #pragma unroll
        for (int o = 0; o < 16; o++) {
            float acc = 0.f;
            #pragma unroll
            for (int j = 0; j < KS; j++) acc += xv[o + j] * w[j];
            pb[(size_t)o * Dn] = __uint_as_float(f2tf(acc));
        }
    } else if (blk == 4096) {
        // ---- Gv/Bv ----
        int j = t;
        float gv = 0.f, bv = 0.f;
        #pragma unroll 8
        for (int d = 0; d < Dn; d++) {
            float w = Wkv[(size_t)d * (2 * Dn) + Dn + j];
            gv += g1[d] * w;
            bv += b1[d] * w;
        }
        g_Gv[j] = gv;
        g_Bv[j] = bv;
    } else if (blk == 4097) {
        // ---- q = cls@Wq; Ag; GA; BA (512 threads) ----
        {
            float a0 = 0.f, a1 = 0.f;
            #pragma unroll 8
            for (int d = 0; d < Dn; d++) {
                a0 += cls[d] * Wq[(size_t)d * Dn + t];
                a1 += cls[Dn + d] * Wq[(size_t)d * Dn + t];
            }
            sq[t] = a0;
            sq[Dn + t] = a1;
        }
        __syncthreads();
        int c = t & 31;
        int h = c >> 1, n = c & 1;
        int dg = t >> 5;                 // 0..15
        float ga = 0.f, ba = 0.f;
        #pragma unroll
        for (int p = 0; p < 32; p++) {
            int d = dg + p * 16;
            float acc = 0.f;
            #pragma unroll
            for (int hd = 0; hd < HDn; hd++)
                acc += Wkv[(size_t)d * (2 * Dn) + h * HDn + hd] * sq[n * Dn + h * HDn + hd];
            acc *= 0.17677669529663687f;
            float ag = g1[d] * acc;
            g_Ag[d * 32 + c] = ag;
            ga += ag;
            ba += b1[d] * acc;
        }
        ra[dg][c] = ga;
        rb[dg][c] = ba;
        __syncthreads();
        if (t < 32) {
            float sga = 0.f, sba = 0.f;
            #pragma unroll
            for (int k = 0; k < 16; k++) { sga += ra[k][t]; sba += rb[k][t]; }
            g_GA[t] = sga;
            g_BA[t] = sba;
        }
    } else {
        // ---- Wp1 -> tf32 (8 blocks x 512 threads x 16 float4) ----
        int bid = blk - 4098;
        const float4* src = (const float4*)Wp1;
        uint4* dst = (uint4*)g_Wp1t;
        #pragma unroll
        for (int v = 0; v < 16; v++) {
            int i4 = bid * 8192 + v * 512 + t;
            float4 f = src[i4];
            uint4 u;
            u.x = f2tf(f.x); u.y = f2tf(f.y); u.z = f2tf(f.z); u.w = f2tf(f.w);
            dst[i4] = u;
        }
    }
}

// ===== GEMM0 (tf32 TC): xnew = pos @ Wp1 + x + bp1 =====
// 128x128 block tile, 8 warps (64x32 warp tiles), K-tile 16.
// Inputs pre-converted to tf32 -> staging is pure copies (no CVT).
#define APAD 20
#define BPAD 136
__global__ void __launch_bounds__(256)
k_gemm0(const float* __restrict__ X, const float* __restrict__ bias) {
    __shared__ unsigned As[2][128][APAD];   // [m][k]
    __shared__ unsigned Bs[2][16][BPAD];    // [k][n]
    int t    = threadIdx.x;
    int brow = blockIdx.y * 128;
    int bcol = blockIdx.x * 128;
    int lane = t & 31, warp = t >> 5;
    int g    = lane >> 2, tig = lane & 3;
    int m0w  = (warp >> 2) * 64;
    int n0w  = (warp & 3) * 32;

    int arow = t >> 1, akh = (t & 1) * 8;
    int bkr  = t >> 4, bn8 = (t & 15) * 8;

    const float*    pA = g_pos + (size_t)(brow + arow) * Dn + akh;
    const unsigned* pB = g_Wp1t + (size_t)bkr * Dn + bcol + bn8;

    float acc[4][4][4];
    #pragma unroll
    for (int i = 0; i < 4; i++)
        #pragma unroll
        for (int j = 0; j < 4; j++)
            #pragma unroll
            for (int k = 0; k < 4; k++) acc[i][j][k] = 0.f;

    {
        uint4 A0 = *(const uint4*)(pA);
        uint4 A1 = *(const uint4*)(pA + 4);
        uint4 B0 = *(const uint4*)(pB);
        uint4 B1 = *(const uint4*)(pB + 4);
        *(uint4*)&As[0][arow][akh]     = A0;
        *(uint4*)&As[0][arow][akh + 4] = A1;
        *(uint4*)&Bs[0][bkr][bn8]      = B0;
        *(uint4*)&Bs[0][bkr][bn8 + 4]  = B1;
    }
    __syncthreads();

    int buf = 0;
    for (int kt = 1; kt <= 32; kt++) {
        bool more = (kt < 32);
        uint4 A0, A1, B0, B1;
        if (more) {
            int k0 = kt * 16;
            A0 = *(const uint4*)(pA + k0);
            A1 = *(const uint4*)(pA + k0 + 4);
            B0 = *(const uint4*)(pB + (size_t)k0 * Dn);
            B1 = *(const uint4*)(pB + (size_t)k0 * Dn + 4);
        }
        #pragma unroll
        for (int ks = 0; ks < 16; ks += 8) {
            unsigned a[4][4], b[4][2];
            #pragma unroll
            for (int i = 0; i < 4; i++) {
                int m = m0w + 16 * i + g;
                a[i][0] = As[buf][m][ks + tig];
                a[i][1] = As[buf][m + 8][ks + tig];
                a[i][2] = As[buf][m][ks + tig + 4];
                a[i][3] = As[buf][m + 8][ks + tig + 4];
            }
            #pragma unroll
            for (int j = 0; j < 4; j++) {
                int n = n0w + 8 * j + g;
                b[j][0] = Bs[buf][ks + tig][n];
                b[j][1] = Bs[buf][ks + tig + 4][n];
            }
            #pragma unroll
            for (int i = 0; i < 4; i++)
                #pragma unroll
                for (int j = 0; j < 4; j++)
                    mma_tf32(acc[i][j], a[i], b[j]);
        }
        if (more) {
            int nb = buf ^ 1;
            *(uint4*)&As[nb][arow][akh]     = A0;
            *(uint4*)&As[nb][arow][akh + 4] = A1;
            *(uint4*)&Bs[nb][bkr][bn8]      = B0;
            *(uint4*)&Bs[nb][bkr][bn8 + 4]  = B1;
        }
        __syncthreads();
        buf ^= 1;
    }

    #pragma unroll
    for (int i = 0; i < 4; i++) {
        #pragma unroll
        for (int j = 0; j < 4; j++) {
            int r1 = brow + m0w + 16 * i + g;
            int r2 = r1 + 8;
            int cc = bcol + n0w + 8 * j + 2 * tig;
            float2 bb = *(const float2*)(bias + cc);
            float2 x1 = *(const float2*)(X + (size_t)r1 * Dn + cc);
            float2 o1 = make_float2(acc[i][j][0] + x1.x + bb.x,
                                    acc[i][j][1] + x1.y + bb.y);
            *(float2*)(g_xnew + (size_t)r1 * Dn + cc) = o1;
            float2 x2 = *(const float2*)(X + (size_t)r2 * Dn + cc);
            float2 o2 = make_float2(acc[i][j][2] + x2.x + bb.x,
                                    acc[i][j][3] + x2.y + bb.y);
            *(float2*)(g_xnew + (size_t)r2 * Dn + cc) = o2;
        }
    }
}

// ===== scores + LN stats: 256 rows x 32 cols per block =====  (PROFILED SLOT)
__global__ void __launch_bounds__(256)
k_scores(float* __restrict__ attn_out) {
    __shared__ float Xs[32][260];
    __shared__ float As2[32][32];
    int t  = threadIdx.x;
    int R0 = blockIdx.x * 256;
    int rgrp = t & 31, cgrp = t >> 5;
    int r0 = rgrp * 8, c0 = cgrp * 4;

    float acc[8][4];
    float s[8], q[8];
    #pragma unroll
    for (int i = 0; i < 8; i++) {
        s[i] = 0.f; q[i] = 0.f;
        #pragma unroll
        for (int j = 0; j < 4; j++) acc[i][j] = 0.f;
    }

    for (int dt = 0; dt < 16; dt++) {
        #pragma unroll
        for (int i = 0; i < 8; i++) {
            int rr  = (t >> 3) + i * 32;
            int dd0 = (t & 7) * 4;
            float4 a4 = *(const float4*)(g_xnew + (size_t)(R0 + rr) * Dn + dt * 32 + dd0);
            Xs[dd0 + 0][rr] = a4.x;
            Xs[dd0 + 1][rr] = a4.y;
            Xs[dd0 + 2][rr] = a4.z;
            Xs[dd0 + 3][rr] = a4.w;
        }
        {
            int dp = t >> 3, c4 = (t & 7) * 4;
            *(float4*)&As2[dp][c4] = *(const float4*)(g_Ag + (dt * 32 + dp) * 32 + c4);
        }
        __syncthreads();
        #pragma unroll
        for (int dd2 = 0; dd2 < 4; dd2++) {
            int dd = cgrp * 4 + dd2;
            float4 va = *(const float4*)&Xs[dd][r0];
            float4 vb = *(const float4*)&Xs[dd][r0 + 4];
            s[0] += va.x; q[0] += va.x * va.x;
            s[1] += va.y; q[1] += va.y * va.y;
            s[2] += va.z; q[2] += va.z * va.z;
            s[3] += va.w; q[3] += va.w * va.w;
            s[4] += vb.x; q[4] += vb.x * vb.x;
            s[5] += vb.y; q[5] += vb.y * vb.y;
            s[6] += vb.z; q[6] += vb.z * vb.z;
            s[7] += vb.w; q[7] += vb.w * vb.w;
        }
        #pragma unroll
        for (int dd = 0; dd < 32; dd++) {
            float xa[8], ab[4];
            *(float4*)&xa[0] = *(const float4*)&Xs[dd][r0];
            *(float4*)&xa[4] = *(const float4*)&Xs[dd][r0 + 4];
            *(float4*)&ab[0] = *(const float4*)&As2[dd][c0];
            #pragma unroll
            for (int i = 0; i < 8; i++)
                #pragma unroll
                for (int j = 0; j < 4; j++) acc[i][j] += xa[i] * ab[j];
        }
        __syncthreads();
    }

    float* sS = &Xs[0][0];
    float* sQ = sS + 2048;
    #pragma unroll
    for (int i = 0; i < 8; i++) {
        sS[cgrp * 256 + r0 + i] = s[i];
        sQ[cgrp * 256 + r0 + i] = q[i];
    }
    __syncthreads();
    float* smM = &As2[0][0];
    float* smR = smM + 256;
    {
        float ssum = 0.f, qsum = 0.f;
        #pragma unroll
        for (int cg = 0; cg < 8; cg++) {
            ssum += sS[cg * 256 + t];
            qsum += sQ[cg * 256 + t];
        }
        float m   = ssum * (1.f / Dn);
        float var = qsum * (1.f / Dn) - m * m;
        float rs  = rsqrtf(var + 1e-5f);
        g_mean[R0 + t] = m;
        g_rstd[R0 + t] = rs;
        smM[t] = m;
        smR[t] = rs;
    }
    __syncthreads();

    #pragma unroll
    for (int i = 0; i < 8; i++) {
        int rl = r0 + i;
        int gr = R0 + rl;
        float rs = smR[rl], mn = smM[rl];
        int b = gr >> 11, sidx = gr & 2047;
        #pragma unroll
        for (int j = 0; j < 4; j++) {
            int c = c0 + j;
            float sc = rs * (acc[i][j] - mn * g_GA[c]) + g_BA[c]
                       - 7.6246189861593985f;
            float a = 1.f / (1.f + expf(-sc));
            attn_out[((size_t)(b * 32 + c)) * Sn + sidx] = a;
        }
    }
}

// ===== z partials + P,Q partials: s split 4 ways =====
__global__ void __launch_bounds__(256)
k_zpq(const float* __restrict__ attn) {
    __shared__ float a_sm[32][36];
    int t  = threadIdx.x;
    int d0 = blockIdx.x * 128;
    int b  = blockIdx.y;
    int sc = blockIdx.z;
    int cq = t >> 5;
    int dq = t & 31;
    int c0 = cq * 4;
    int d  = d0 + dq * 4;
    bool dopq = (blockIdx.x == 0);

    float acc[4][4];
    #pragma unroll
    for (int j = 0; j < 4; j++)
        #pragma unroll
        for (int k = 0; k < 4; k++) acc[j][k] = 0.f;
    float Pl = 0.f, Ql = 0.f;

    int lc  = t >> 3;
    int ls4 = (t & 7) * 4;
    int sbeg = sc * 512;
    for (int s0 = sbeg; s0 < sbeg + 512; s0 += 32) {
        {
            float4 a4 = *(const float4*)(attn + ((size_t)(b * 32 + lc)) * Sn + s0 + ls4);
            float4 r4 = *(const float4*)(g_rstd + b * Sn + s0 + ls4);
            if (dopq) {
                float4 m4 = *(const float4*)(g_mean + b * Sn + s0 + ls4);
                Pl += a4.x + a4.y + a4.z + a4.w;
                Ql += a4.x * r4.x * m4.x + a4.y * r4.y * m4.y
                    + a4.z * r4.z * m4.z + a4.w * r4.w * m4.w;
            }
            a4.x *= r4.x; a4.y *= r4.y; a4.z *= r4.z; a4.w *= r4.w;
            *(float4*)&a_sm[lc][ls4] = a4;
        }
        __syncthreads();
        #pragma unroll 8
        for (int si = 0; si < 32; si++) {
            float4 xv = *(const float4*)(g_xnew + (size_t)(b * Sn + s0 + si) * Dn + d);
            #pragma unroll
            for (int j = 0; j < 4; j++) {
                float av = a_sm[c0 + j][si];
                acc[j][0] += av * xv.x;
                acc[j][1] += av * xv.y;
                acc[j][2] += av * xv.z;
                acc[j][3] += av * xv.w;
            }
        }
        __syncthreads();
    }
    #pragma unroll
    for (int j = 0; j < 4; j++) {
        float4 o4 = make_float4(acc[j][0], acc[j][1], acc[j][2], acc[j][3]);
        *(float4*)(g_zp + (size_t)(((sc * Bn + b) * 32) + c0 + j) * Dn + d) = o4;
    }
    if (dopq) {
        Pl += __shfl_down_sync(0xffffffffu, Pl, 4, 8);
        Pl += __shfl_down_sync(0xffffffffu, Pl, 2, 8);
        Pl += __shfl_down_sync(0xffffffffu, Pl, 1, 8);
        Ql += __shfl_down_sync(0xffffffffu, Ql, 4, 8);
        Ql += __shfl_down_sync(0xffffffffu, Ql, 2, 8);
        Ql += __shfl_down_sync(0xffffffffu, Ql, 1, 8);
        if ((t & 7) == 0) {
            g_Pp[sc * (Bn * 32) + b * 32 + lc] = Pl;
            g_Qp[sc * (Bn * 32) + b * 32 + lc] = Ql;
        }
    }
}

// ===== fused o + head: per (b,n) block; sums the 4 z/P/Q partials =====
__global__ void __launch_bounds__(256)
k_ohead(const float* __restrict__ Wkv, const float* __restrict__ g1,
        const float* __restrict__ Wproj, const float* __restrict__ bproj,
        const float* __restrict__ g2, const float* __restrict__ b2,
        const float* __restrict__ Wc1, const float* __restrict__ bc1,
        const float* __restrict__ Wc2, const float* __restrict__ bc2,
        float* __restrict__ out) {
    __shared__ float zs[16][512];
    __shared__ float row[Dn];
    __shared__ float tmp[Dn];
    __shared__ float red[256];
    __shared__ float sg1[Dn];
    int b = blockIdx.x, n = blockIdx.y;
    int t = threadIdx.x;
    int hh = t >> 5;
    int hd = t & 31;

    sg1[t] = g1[t];
    sg1[t + 256] = g1[t + 256];
    __syncthreads();
    for (int idx = t; idx < 16 * 512; idx += 256) {
        int h = idx >> 9, d = idx & 511;
        size_t base = (size_t)((b * 32) + h * 2 + n) * Dn + d;
        float zsum = g_zp[base]
                   + g_zp[(size_t)(Bn * 32) * Dn + base]
                   + g_zp[2 * (size_t)(Bn * 32) * Dn + base]
                   + g_zp[3 * (size_t)(Bn * 32) * Dn + base];
        zs[h][d] = zsum * sg1[d];
    }
    __syncthreads();

    #pragma unroll
    for (int hi = 0; hi < 2; hi++) {
        int h = hh + hi * 8;
        int j = h * HDn + hd;
        float acc = 0.f;
        for (int d = 0; d < Dn; d++)
            acc += zs[h][d] * Wkv[(size_t)d * (2 * Dn) + Dn + j];
        int c = h * 2 + n;
        float Pv = g_Pp[b * 32 + c] + g_Pp[1024 + b * 32 + c]
                 + g_Pp[2048 + b * 32 + c] + g_Pp[3072 + b * 32 + c];
        float Qv = g_Qp[b * 32 + c] + g_Qp[1024 + b * 32 + c]
                 + g_Qp[2048 + b * 32 + c] + g_Qp[3072 + b * 32 + c];
        row[j] = acc - Qv * g_Gv[j] + Pv * g_Bv[j];
    }
    __syncthreads();

    float a0 = 0.f, a1 = 0.f;
    for (int d = 0; d < Dn; d++) {
        float rv = row[d];
        a0 += rv * Wproj[d * Dn + t];
        a1 += rv * Wproj[d * Dn + t + 256];
    }
    tmp[t]       = a0 + bproj[t];
    tmp[t + 256] = a1 + bproj[t + 256];
    __syncthreads();

    float ps  = tmp[t] + tmp[t + 256];
    float pss = tmp[t] * tmp[t] + tmp[t + 256] * tmp[t + 256];
    red[t] = ps; __syncthreads();
    for (int o = 128; o > 0; o >>= 1) { if (t < o) red[t] += red[t + o]; __syncthreads(); }
    float mean = red[0] * (1.f / Dn);
    __syncthreads();
    red[t] = pss; __syncthreads();
    for (int o = 128; o > 0; o >>= 1) { if (t < o) red[t] += red[t + o]; __syncthreads(); }
    float var  = red[0] * (1.f / Dn) - mean * mean;
    float rstd = rsqrtf(var + 1e-5f);
    __syncthreads();

    row[t]       = (tmp[t] - mean) * rstd * g2[t] + b2[t];
    row[t + 256] = (tmp[t + 256] - mean) * rstd * g2[t + 256] + b2[t + 256];
    __syncthreads();

    float c0 = 0.f, c1 = 0.f;
    for (int d = 0; d < Dn; d++) {
        float rv = row[d];
        c0 += rv * Wc1[d * Dn + t];
        c1 += rv * Wc1[d * Dn + t + 256];
    }
    c0 = fmaxf(c0 + bc1[t], 0.f);
    c1 = fmaxf(c1 + bc1[t + 256], 0.f);
    float part = c0 * Wc2[t] + c1 * Wc2[t + 256];
    red[t] = part; __syncthreads();
    for (int o = 128; o > 0; o >>= 1) { if (t < o) red[t] += red[t + o]; __syncthreads(); }
    if (t == 0) out[b * NCLSn + n] = red[0] + bc2[0];
}

// ===== launch =====
extern "C" void kernel_launch(void* const* d_in, const int* in_sizes, int n_in,
                              void* d_out, int out_size) {
    const float* x     = (const float*)d_in[0];
    const float* wave1 = (const float*)d_in[1];
    const float* wave2 = (const float*)d_in[2];
    const float* wave3 = (const float*)d_in[3];
    const float* Wp1   = (const float*)d_in[4];
    const float* bp1   = (const float*)d_in[5];
    const float* cls   = (const float*)d_in[6];
    const float* ln1g  = (const float*)d_in[7];
    const float* ln1b  = (const float*)d_in[8];
    const float* Wq    = (const float*)d_in[9];
    const float* Wkv   = (const float*)d_in[10];
    const float* Wproj = (const float*)d_in[11];
    const float* bproj = (const float*)d_in[12];
    const float* ln2g  = (const float*)d_in[13];
    const float* ln2b  = (const float*)d_in[14];
    const float* Wc1   = (const float*)d_in[15];
    const float* bc1   = (const float*)d_in[16];
    const float* Wc2   = (const float*)d_in[17];
    const float* bc2   = (const float*)d_in[18];
    float* out = (float*)d_out;
    float* attn = out + Bn * NCLSn;

    k_ksum<<<1, 512>>>(wave1, wave2, wave3);                          // 1
    k_mega<<<4106, 512>>>(x, Wkv, ln1g, ln1b, cls, Wq, Wp1);          // 2
    k_gemm0<<<dim3(4, 512), 256>>>(x, bp1);                           // 3
    k_scores<<<256, 256>>>(attn);                                     // 4  <- profiled
    k_zpq<<<dim3(4, Bn, 4), 256>>>(attn);                             // 5
    k_ohead<<<dim3(Bn, NCLSn), 256>>>(Wkv, ln1g, Wproj, bproj,
                                      ln2g, ln2b, Wc1, bc1, Wc2, bc2, out); // 6
}

// round 12
// speedup vs baseline: 1.6610x; 1.0482x over previous
#include <cuda_runtime.h>
#include <math.h>

// ===== problem constants =====
#define Bn    32
#define Sn    2048
#define Dn    512
#define NCLSn 2
#define Hn    16
#define HDn   32
#define Rn    (Bn*Sn)      // 65536 rows
#define KS    19

// ===== scratch =====
__device__ float    g_kT[KS*Dn];
__device__ float    g_Ag[Dn*32];
__device__ float    g_GA[32];
__device__ float    g_BA[32];
__device__ float    g_Gv[Dn];
__device__ float    g_Bv[Dn];
__device__ unsigned g_Wp1t[Dn*Dn];     // tf32-converted Wp1
__device__ float    g_pos[Rn*Dn];      // 128 MB (tf32-rounded values)
__device__ float    g_xnew[Rn*Dn];     // 128 MB
__device__ float    g_mean[Rn];
__device__ float    g_rstd[Rn];
__device__ float    g_zp[4*Bn*32*Dn];  // 8 MB, partial z per s-chunk
__device__ float    g_Pp[4*Bn*32];
__device__ float    g_Qp[4*Bn*32];

// ===== tf32 helpers =====
__device__ __forceinline__ unsigned f2tf(float x) {
    unsigned u;
    asm("cvt.rna.tf32.f32 %0, %1;" : "=r"(u) : "f"(x));
    return u;
}
__device__ __forceinline__ void mma_tf32(float* c, const unsigned* a, const unsigned* b) {
    asm volatile(
        "mma.sync.aligned.m16n8k8.row.col.f32.tf32.tf32.f32 "
        "{%0,%1,%2,%3},{%4,%5,%6,%7},{%8,%9},{%0,%1,%2,%3};"
        : "+f"(c[0]), "+f"(c[1]), "+f"(c[2]), "+f"(c[3])
        : "r"(a[0]), "r"(a[1]), "r"(a[2]), "r"(a[3]), "r"(b[0]), "r"(b[1]));
}

// ===== tiny: summed mexican-hat kernel =====
__global__ void __launch_bounds__(512)
k_ksum(const float* __restrict__ w1, const float* __restrict__ w2,
       const float* __restrict__ w3) {
    int d = threadIdx.x;
    const float C = 0.8673250705840776f;
    float out[KS];
    #pragma unroll
    for (int j = 0; j < KS; j++) out[j] = 0.f;
    const float* ws[3] = {w1, w2, w3};
    for (int w = 0; w < 3; w++) {
        float scale = ws[w][d];
        float shift = ws[w][Dn + d];
        float inv   = 1.f / scale;
        float amp   = C * rsqrtf(fabsf(scale));
        #pragma unroll
        for (int j = 0; j < KS; j++) {
            float xg = (float)(j - 9) - shift;
            float u  = xg * inv;
            out[j] += amp * (1.f - u * u) * expf(-0.5f * u * u);
        }
    }
    #pragma unroll
    for (int j = 0; j < KS; j++) g_kT[j * Dn + d] = out[j];
}

// ===== mega: conv (blocks 0..4095) + GvBv (4096) + qA (4097) + Wp1cvt (4098..4105) =====
__global__ void __launch_bounds__(512)
k_mega(const float* __restrict__ x, const float* __restrict__ Wkv,
       const float* __restrict__ g1, const float* __restrict__ b1,
       const float* __restrict__ cls, const float* __restrict__ Wq,
       const float* __restrict__ Wp1) {
    __shared__ float sq[NCLSn * Dn];
    __shared__ float ra[16][33];
    __shared__ float rb[16][33];
    int t = threadIdx.x;
    int blk = blockIdx.x;

    if (blk < 4096) {
        int b  = blk >> 7;
        int s0 = (blk & 127) * 16;
        int d  = t;
        const float* xb = x + (size_t)b * Sn * Dn;
        float w[KS];
        #pragma unroll
        for (int j = 0; j < KS; j++) w[j] = g_kT[j * Dn + d];
        float xv[34];
        #pragma unroll
        for (int l = 0; l < 34; l++) {
            int ss = s0 - 9 + l;
            xv[l] = ((unsigned)ss < (unsigned)Sn) ? xb[(size_t)ss * Dn + d] : 0.f;
        }
        float* pb = g_pos + ((size_t)(b * Sn + s0)) * Dn + d;
        #pragma unroll
        for (int o = 0; o < 16; o++) {
            float acc = 0.f;
            #pragma unroll
            for (int j = 0; j < KS; j++) acc += xv[o + j] * w[j];
            pb[(size_t)o * Dn] = __uint_as_float(f2tf(acc));
        }
    } else if (blk == 4096) {
        int j = t;
        float gv = 0.f, bv = 0.f;
        #pragma unroll 8
        for (int d = 0; d < Dn; d++) {
            float w = Wkv[(size_t)d * (2 * Dn) + Dn + j];
            gv += g1[d] * w;
            bv += b1[d] * w;
        }
        g_Gv[j] = gv;
        g_Bv[j] = bv;
    } else if (blk == 4097) {
        {
            float a0 = 0.f, a1 = 0.f;
            #pragma unroll 8
            for (int d = 0; d < Dn; d++) {
                a0 += cls[d] * Wq[(size_t)d * Dn + t];
                a1 += cls[Dn + d] * Wq[(size_t)d * Dn + t];
            }
            sq[t] = a0;
            sq[Dn + t] = a1;
        }
        __syncthreads();
        int c = t & 31;
        int h = c >> 1, n = c & 1;
        int dg = t >> 5;
        float ga = 0.f, ba = 0.f;
        #pragma unroll
        for (int p = 0; p < 32; p++) {
            int d = dg + p * 16;
            float acc = 0.f;
            #pragma unroll
            for (int hd = 0; hd < HDn; hd++)
                acc += Wkv[(size_t)d * (2 * Dn) + h * HDn + hd] * sq[n * Dn + h * HDn + hd];
            acc *= 0.17677669529663687f;
            float ag = g1[d] * acc;
            g_Ag[d * 32 + c] = ag;
            ga += ag;
            ba += b1[d] * acc;
        }
        ra[dg][c] = ga;
        rb[dg][c] = ba;
        __syncthreads();
        if (t < 32) {
            float sga = 0.f, sba = 0.f;
            #pragma unroll
            for (int k = 0; k < 16; k++) { sga += ra[k][t]; sba += rb[k][t]; }
            g_GA[t] = sga;
            g_BA[t] = sba;
        }
    } else {
        int bid = blk - 4098;
        const float4* src = (const float4*)Wp1;
        uint4* dst = (uint4*)g_Wp1t;
        #pragma unroll
        for (int v = 0; v < 16; v++) {
            int i4 = bid * 8192 + v * 512 + t;
            float4 f = src[i4];
            uint4 u;
            u.x = f2tf(f.x); u.y = f2tf(f.y); u.z = f2tf(f.z); u.w = f2tf(f.w);
            dst[i4] = u;
        }
    }
}

// ===== GEMM0 (tf32 TC): xnew = pos @ Wp1 + x + bp1 =====
#define APAD 20
#define BPAD 136
__global__ void __launch_bounds__(256)
k_gemm0(const float* __restrict__ X, const float* __restrict__ bias) {
    __shared__ unsigned As[2][128][APAD];   // [m][k]
    __shared__ unsigned Bs[2][16][BPAD];    // [k][n]
    int t    = threadIdx.x;
    int brow = blockIdx.y * 128;
    int bcol = blockIdx.x * 128;
    int lane = t & 31, warp = t >> 5;
    int g    = lane >> 2, tig = lane & 3;
    int m0w  = (warp >> 2) * 64;
    int n0w  = (warp & 3) * 32;

    int arow = t >> 1, akh = (t & 1) * 8;
    int bkr  = t >> 4, bn8 = (t & 15) * 8;

    const float*    pA = g_pos + (size_t)(brow + arow) * Dn + akh;
    const unsigned* pB = g_Wp1t + (size_t)bkr * Dn + bcol + bn8;

    float acc[4][4][4];
    #pragma unroll
    for (int i = 0; i < 4; i++)
        #pragma unroll
        for (int j = 0; j < 4; j++)
            #pragma unroll
            for (int k = 0; k < 4; k++) acc[i][j][k] = 0.f;

    {
        uint4 A0 = *(const uint4*)(pA);
        uint4 A1 = *(const uint4*)(pA + 4);
        uint4 B0 = *(const uint4*)(pB);
        uint4 B1 = *(const uint4*)(pB + 4);
        *(uint4*)&As[0][arow][akh]     = A0;
        *(uint4*)&As[0][arow][akh + 4] = A1;
        *(uint4*)&Bs[0][bkr][bn8]      = B0;
        *(uint4*)&Bs[0][bkr][bn8 + 4]  = B1;
    }
    __syncthreads();

    int buf = 0;
    for (int kt = 1; kt <= 32; kt++) {
        bool more = (kt < 32);
        uint4 A0, A1, B0, B1;
        if (more) {
            int k0 = kt * 16;
            A0 = *(const uint4*)(pA + k0);
            A1 = *(const uint4*)(pA + k0 + 4);
            B0 = *(const uint4*)(pB + (size_t)k0 * Dn);
            B1 = *(const uint4*)(pB + (size_t)k0 * Dn + 4);
        }
        #pragma unroll
        for (int ks = 0; ks < 16; ks += 8) {
            unsigned a[4][4], b[4][2];
            #pragma unroll
            for (int i = 0; i < 4; i++) {
                int m = m0w + 16 * i + g;
                a[i][0] = As[buf][m][ks + tig];
                a[i][1] = As[buf][m + 8][ks + tig];
                a[i][2] = As[buf][m][ks + tig + 4];
                a[i][3] = As[buf][m + 8][ks + tig + 4];
            }
            #pragma unroll
            for (int j = 0; j < 4; j++) {
                int n = n0w + 8 * j + g;
                b[j][0] = Bs[buf][ks + tig][n];
                b[j][1] = Bs[buf][ks + tig + 4][n];
            }
            #pragma unroll
            for (int i = 0; i < 4; i++)
                #pragma unroll
                for (int j = 0; j < 4; j++)
                    mma_tf32(acc[i][j], a[i], b[j]);
        }
        if (more) {
            int nb = buf ^ 1;
            *(uint4*)&As[nb][arow][akh]     = A0;
            *(uint4*)&As[nb][arow][akh + 4] = A1;
            *(uint4*)&Bs[nb][bkr][bn8]      = B0;
            *(uint4*)&Bs[nb][bkr][bn8 + 4]  = B1;
        }
        __syncthreads();
        buf ^= 1;
    }

    #pragma unroll
    for (int i = 0; i < 4; i++) {
        #pragma unroll
        for (int j = 0; j < 4; j++) {
            int r1 = brow + m0w + 16 * i + g;
            int r2 = r1 + 8;
            int cc = bcol + n0w + 8 * j + 2 * tig;
            float2 bb = *(const float2*)(bias + cc);
            float2 x1 = *(const float2*)(X + (size_t)r1 * Dn + cc);
            float2 o1 = make_float2(acc[i][j][0] + x1.x + bb.x,
                                    acc[i][j][1] + x1.y + bb.y);
            *(float2*)(g_xnew + (size_t)r1 * Dn + cc) = o1;
            float2 x2 = *(const float2*)(X + (size_t)r2 * Dn + cc);
            float2 o2 = make_float2(acc[i][j][2] + x2.x + bb.x,
                                    acc[i][j][3] + x2.y + bb.y);
            *(float2*)(g_xnew + (size_t)r2 * Dn + cc) = o2;
        }
    }
}

// ===== scores + LN stats: 128 rows x 32 cols per block, conflict-free =====
// Each thread owns 4 rows strided by 32 (lane-consecutive LDS). (PROFILED SLOT)
__global__ void __launch_bounds__(256)
k_scores(float* __restrict__ attn_out) {
    __shared__ float Xs[32][133];   // [dd][r], reused as stats scratch
    __shared__ float As2[32][32];   // [dd][c], reused as mean/rstd broadcast
    int t    = threadIdx.x;
    int R0   = blockIdx.x * 128;
    int lane = t & 31, cgrp = t >> 5;   // 8 warps x 4 cols
    int c0   = cgrp * 4;

    float acc[4][4];
    float s[4], q[4];
    #pragma unroll
    for (int i = 0; i < 4; i++) {
        s[i] = 0.f; q[i] = 0.f;
        #pragma unroll
        for (int j = 0; j < 4; j++) acc[i][j] = 0.f;
    }

    for (int dt = 0; dt < 16; dt++) {
        // load X tile: 128 rows x 32 dd (transposed into Xs[dd][r])
        #pragma unroll
        for (int i2 = 0; i2 < 4; i2++) {
            int rr  = (t >> 3) + i2 * 32;
            int dd0 = (t & 7) * 4;
            float4 a4 = *(const float4*)(g_xnew + (size_t)(R0 + rr) * Dn + dt * 32 + dd0);
            Xs[dd0 + 0][rr] = a4.x;
            Xs[dd0 + 1][rr] = a4.y;
            Xs[dd0 + 2][rr] = a4.z;
            Xs[dd0 + 3][rr] = a4.w;
        }
        {
            int dp = t >> 3, c4 = (t & 7) * 4;
            *(float4*)&As2[dp][c4] = *(const float4*)(g_Ag + (dt * 32 + dp) * 32 + c4);
        }
        __syncthreads();
        // LN stats partials: warp cgrp covers dd in [cgrp*4, cgrp*4+4)
        #pragma unroll
        for (int dd2 = 0; dd2 < 4; dd2++) {
            int dd = cgrp * 4 + dd2;
            #pragma unroll
            for (int i = 0; i < 4; i++) {
                float v = Xs[dd][lane + 32 * i];
                s[i] += v;
                q[i] += v * v;
            }
        }
        // GEMM: conflict-free scalar xa loads (lane-consecutive)
        #pragma unroll
        for (int dd = 0; dd < 32; dd++) {
            float ab[4];
            *(float4*)&ab[0] = *(const float4*)&As2[dd][c0];
            #pragma unroll
            for (int i = 0; i < 4; i++) {
                float xv = Xs[dd][lane + 32 * i];
                acc[i][0] += xv * ab[0];
                acc[i][1] += xv * ab[1];
                acc[i][2] += xv * ab[2];
                acc[i][3] += xv * ab[3];
            }
        }
        __syncthreads();
    }

    // reduce stats across 8 warps (Xs reused)
    float* sS = &Xs[0][0];          // 1024 floats
    float* sQ = sS + 1024;          // 1024 floats (Xs has 4256)
    #pragma unroll
    for (int i = 0; i < 4; i++) {
        sS[cgrp * 128 + lane + 32 * i] = s[i];
        sQ[cgrp * 128 + lane + 32 * i] = q[i];
    }
    __syncthreads();
    float* smM = &As2[0][0];        // 128 floats
    float* smR = smM + 128;         // 128 floats
    if (t < 128) {
        float ssum = 0.f, qsum = 0.f;
        #pragma unroll
        for (int cg = 0; cg < 8; cg++) {
            ssum += sS[cg * 128 + t];
            qsum += sQ[cg * 128 + t];
        }
        float m   = ssum * (1.f / Dn);
        float var = qsum * (1.f / Dn) - m * m;
        float rs  = rsqrtf(var + 1e-5f);
        g_mean[R0 + t] = m;
        g_rstd[R0 + t] = rs;
        smM[t] = m;
        smR[t] = rs;
    }
    __syncthreads();

    #pragma unroll
    for (int i = 0; i < 4; i++) {
        int rl = lane + 32 * i;
        int gr = R0 + rl;
        float rs = smR[rl], mn = smM[rl];
        int b = gr >> 11, sidx = gr & 2047;
        #pragma unroll
        for (int j = 0; j < 4; j++) {
            int c = c0 + j;
            float sc = rs * (acc[i][j] - mn * g_GA[c]) + g_BA[c]
                       - 7.6246189861593985f;
            float a = 1.f / (1.f + expf(-sc));
            attn_out[((size_t)(b * 32 + c)) * Sn + sidx] = a;
        }
    }
}

// ===== z partials + P,Q partials: s split 4 ways =====
__global__ void __launch_bounds__(256)
k_zpq(const float* __restrict__ attn) {
    __shared__ float a_sm[32][36];
    int t  = threadIdx.x;
    int d0 = blockIdx.x * 128;
    int b  = blockIdx.y;
    int sc = blockIdx.z;
    int cq = t >> 5;
    int dq = t & 31;
    int c0 = cq * 4;
    int d  = d0 + dq * 4;
    bool dopq = (blockIdx.x == 0);

    float acc[4][4];
    #pragma unroll
    for (int j = 0; j < 4; j++)
        #pragma unroll
        for (int k = 0; k < 4; k++) acc[j][k] = 0.f;
    float Pl = 0.f, Ql = 0.f;

    int lc  = t >> 3;
    int ls4 = (t & 7) * 4;
    int sbeg = sc * 512;
    for (int s0 = sbeg; s0 < sbeg + 512; s0 += 32) {
        {
            float4 a4 = *(const float4*)(attn + ((size_t)(b * 32 + lc)) * Sn + s0 + ls4);
            float4 r4 = *(const float4*)(g_rstd + b * Sn + s0 + ls4);
            if (dopq) {
                float4 m4 = *(const float4*)(g_mean + b * Sn + s0 + ls4);
                Pl += a4.x + a4.y + a4.z + a4.w;
                Ql += a4.x * r4.x * m4.x + a4.y * r4.y * m4.y
                    + a4.z * r4.z * m4.z + a4.w * r4.w * m4.w;
            }
            a4.x *= r4.x; a4.y *= r4.y; a4.z *= r4.z; a4.w *= r4.w;
            *(float4*)&a_sm[lc][ls4] = a4;
        }
        __syncthreads();
        #pragma unroll 8
        for (int si = 0; si < 32; si++) {
            float4 xv = *(const float4*)(g_xnew + (size_t)(b * Sn + s0 + si) * Dn + d);
            #pragma unroll
            for (int j = 0; j < 4; j++) {
                float av = a_sm[c0 + j][si];
                acc[j][0] += av * xv.x;
                acc[j][1] += av * xv.y;
                acc[j][2] += av * xv.z;
                acc[j][3] += av * xv.w;
            }
        }
        __syncthreads();
    }
    #pragma unroll
    for (int j = 0; j < 4; j++) {
        float4 o4 = make_float4(acc[j][0], acc[j][1], acc[j][2], acc[j][3]);
        *(float4*)(g_zp + (size_t)(((sc * Bn + b) * 32) + c0 + j) * Dn + d) = o4;
    }
    if (dopq) {
        Pl += __shfl_down_sync(0xffffffffu, Pl, 4, 8);
        Pl += __shfl_down_sync(0xffffffffu, Pl, 2, 8);
        Pl += __shfl_down_sync(0xffffffffu, Pl, 1, 8);
        Ql += __shfl_down_sync(0xffffffffu, Ql, 4, 8);
        Ql += __shfl_down_sync(0xffffffffu, Ql, 2, 8);
        Ql += __shfl_down_sync(0xffffffffu, Ql, 1, 8);
        if ((t & 7) == 0) {
            g_Pp[sc * (Bn * 32) + b * 32 + lc] = Pl;
            g_Qp[sc * (Bn * 32) + b * 32 + lc] = Ql;
        }
    }
}

// ===== fused o + head: per (b,n) block; sums the 4 z/P/Q partials =====
__global__ void __launch_bounds__(256)
k_ohead(const float* __restrict__ Wkv, const float* __restrict__ g1,
        const float* __restrict__ Wproj, const float* __restrict__ bproj,
        const float* __restrict__ g2, const float* __restrict__ b2,
        const float* __restrict__ Wc1, const float* __restrict__ bc1,
        const float* __restrict__ Wc2, const float* __restrict__ bc2,
        float* __restrict__ out) {
    __shared__ float zs[16][512];
    __shared__ float row[Dn];
    __shared__ float tmp[Dn];
    __shared__ float red[256];
    __shared__ float sg1[Dn];
    int b = blockIdx.x, n = blockIdx.y;
    int t = threadIdx.x;
    int hh = t >> 5;
    int hd = t & 31;

    sg1[t] = g1[t];
    sg1[t + 256] = g1[t + 256];
    __syncthreads();
    for (int idx = t; idx < 16 * 512; idx += 256) {
        int h = idx >> 9, d = idx & 511;
        size_t base = (size_t)((b * 32) + h * 2 + n) * Dn + d;
        float zsum = g_zp[base]
                   + g_zp[(size_t)(Bn * 32) * Dn + base]
                   + g_zp[2 * (size_t)(Bn * 32) * Dn + base]
                   + g_zp[3 * (size_t)(Bn * 32) * Dn + base];
        zs[h][d] = zsum * sg1[d];
    }
    __syncthreads();

    #pragma unroll
    for (int hi = 0; hi < 2; hi++) {
        int h = hh + hi * 8;
        int j = h * HDn + hd;
        float acc = 0.f;
        for (int d = 0; d < Dn; d++)
            acc += zs[h][d] * Wkv[(size_t)d * (2 * Dn) + Dn + j];
        int c = h * 2 + n;
        float Pv = g_Pp[b * 32 + c] + g_Pp[1024 + b * 32 + c]
                 + g_Pp[2048 + b * 32 + c] + g_Pp[3072 + b * 32 + c];
        float Qv = g_Qp[b * 32 + c] + g_Qp[1024 + b * 32 + c]
                 + g_Qp[2048 + b * 32 + c] + g_Qp[3072 + b * 32 + c];
        row[j] = acc - Qv * g_Gv[j] + Pv * g_Bv[j];
    }
    __syncthreads();

    float a0 = 0.f, a1 = 0.f;
    for (int d = 0; d < Dn; d++) {
        float rv = row[d];
        a0 += rv * Wproj[d * Dn + t];
        a1 += rv * Wproj[d * Dn + t + 256];
    }
    tmp[t]       = a0 + bproj[t];
    tmp[t + 256] = a1 + bproj[t + 256];
    __syncthreads();

    float ps  = tmp[t] + tmp[t + 256];
    float pss = tmp[t] * tmp[t] + tmp[t + 256] * tmp[t + 256];
    red[t] = ps; __syncthreads();
    for (int o = 128; o > 0; o >>= 1) { if (t < o) red[t] += red[t + o]; __syncthreads(); }
    float mean = red[0] * (1.f / Dn);
    __syncthreads();
    red[t] = pss; __syncthreads();
    for (int o = 128; o > 0; o >>= 1) { if (t < o) red[t] += red[t + o]; __syncthreads(); }
    float var  = red[0] * (1.f / Dn) - mean * mean;
    float rstd = rsqrtf(var + 1e-5f);
    __syncthreads();

    row[t]       = (tmp[t] - mean) * rstd * g2[t] + b2[t];
    row[t + 256] = (tmp[t + 256] - mean) * rstd * g2[t + 256] + b2[t + 256];
    __syncthreads();

    float c0 = 0.f, c1 = 0.f;
    for (int d = 0; d < Dn; d++) {
        float rv = row[d];
        c0 += rv * Wc1[d * Dn + t];
        c1 += rv * Wc1[d * Dn + t + 256];
    }
    c0 = fmaxf(c0 + bc1[t], 0.f);
    c1 = fmaxf(c1 + bc1[t + 256], 0.f);
    float part = c0 * Wc2[t] + c1 * Wc2[t + 256];
    red[t] = part; __syncthreads();
    for (int o = 128; o > 0; o >>= 1) { if (t < o) red[t] += red[t + o]; __syncthreads(); }
    if (t == 0) out[b * NCLSn + n] = red[0] + bc2[0];
}

// ===== launch =====
extern "C" void kernel_launch(void* const* d_in, const int* in_sizes, int n_in,
                              void* d_out, int out_size) {
    const float* x     = (const float*)d_in[0];
    const float* wave1 = (const float*)d_in[1];
    const float* wave2 = (const float*)d_in[2];
    const float* wave3 = (const float*)d_in[3];
    const float* Wp1   = (const float*)d_in[4];
    const float* bp1   = (const float*)d_in[5];
    const float* cls   = (const float*)d_in[6];
    const float* ln1g  = (const float*)d_in[7];
    const float* ln1b  = (const float*)d_in[8];
    const float* Wq    = (const float*)d_in[9];
    const float* Wkv   = (const float*)d_in[10];
    const float* Wproj = (const float*)d_in[11];
    const float* bproj = (const float*)d_in[12];
    const float* ln2g  = (const float*)d_in[13];
    const float* ln2b  = (const float*)d_in[14];
    const float* Wc1   = (const float*)d_in[15];
    const float* bc1   = (const float*)d_in[16];
    const float* Wc2   = (const float*)d_in[17];
    const float* bc2   = (const float*)d_in[18];
    float* out = (float*)d_out;
    float* attn = out + Bn * NCLSn;

    k_ksum<<<1, 512>>>(wave1, wave2, wave3);                          // 1
    k_mega<<<4106, 512>>>(x, Wkv, ln1g, ln1b, cls, Wq, Wp1);          // 2
    k_gemm0<<<dim3(4, 512), 256>>>(x, bp1);                           // 3
    k_scores<<<512, 256>>>(attn);                                     // 4  <- profiled
    k_zpq<<<dim3(4, Bn, 4), 256>>>(attn);                             // 5
    k_ohead<<<dim3(Bn, NCLSn), 256>>>(Wkv, ln1g, Wproj, bproj,
                                      ln2g, ln2b, Wc1, bc1, Wc2, bc2, out); // 6
}